// round 1
// baseline (speedup 1.0000x reference)
#include <cuda_runtime.h>
#include <math.h>

#define DIM 128
#define NMAX 100000

// Scratch (allocation-free rule: __device__ globals)
__device__ float g_bufA[(size_t)NMAX * DIM];   // hs (messages, pre-scaled by dinv[src])
__device__ float g_bufB[(size_t)NMAX * DIM];   // accumulator / activations
__device__ int   g_deg[NMAX];
__device__ float g_dinv[NMAX];
__device__ int   g_is64;

// ---------------- index dtype detection + loader ----------------
__global__ void detect_kernel(const unsigned int* __restrict__ p) {
    if (threadIdx.x == 0 && blockIdx.x == 0) {
        int is64 = 1;
        #pragma unroll
        for (int i = 0; i < 64; i++)
            if (p[2 * i + 1] != 0u) is64 = 0;
        g_is64 = is64;
    }
}

__device__ __forceinline__ int ld_idx(const void* p, long long i) {
    if (g_is64) return (int)((const long long*)p)[i];
    return ((const int*)p)[i];
}

// ---------------- degree / norm ----------------
__global__ void deg_init(int n) {
    int i = blockIdx.x * blockDim.x + threadIdx.x;
    if (i < n) g_deg[i] = 1;  // self-loop
}

__global__ void deg_count(const void* __restrict__ ei, long long E) {
    long long i = (long long)blockIdx.x * blockDim.x + threadIdx.x;
    if (i < E) atomicAdd(&g_deg[ld_idx(ei, E + i)], 1);
}

__global__ void dinv_kernel(int n) {
    int i = blockIdx.x * blockDim.x + threadIdx.x;
    if (i < n) g_dinv[i] = rsqrtf((float)g_deg[i]);
}

// ---------------- fp32 GEMM: out = (X @ W) * dinv[row], written to outA and outB ----------------
// Block: 256 threads, 32 rows per block. W (64KB) + X tile (16KB) in dynamic smem.
// Thread (ri,ci) computes 4 rows x 4 cols micro-tile; x reads are smem broadcasts,
// W reads are conflict-free LDS.128.
#define GEMM_SMEM ((DIM * DIM + 32 * DIM) * sizeof(float))

__global__ void gemm_scaled(const float* __restrict__ X, const float* __restrict__ W,
                            float* __restrict__ outA, float* __restrict__ outB, int n) {
    extern __shared__ float sm[];
    float* sW = sm;            // [128][128]
    float* sX = sm + DIM * DIM; // [32][128]
    int t = threadIdx.x;

    const float4* W4 = (const float4*)W;
    float4* sW4 = (float4*)sW;
    #pragma unroll
    for (int i = 0; i < 16; i++) sW4[t + 256 * i] = W4[t + 256 * i];

    int row0 = blockIdx.x * 32;
    const float4* X4 = (const float4*)X;
    float4* sX4 = (float4*)sX;
    #pragma unroll
    for (int i = 0; i < 4; i++) {
        int q = t + 256 * i;
        int r = q >> 5, c4 = q & 31;
        int row = row0 + r;
        float4 f = (row < n) ? X4[(size_t)row * 32 + c4] : make_float4(0.f, 0.f, 0.f, 0.f);
        sX4[r * 32 + c4] = f;
    }
    __syncthreads();

    int ci = t & 31;       // column group: cols 4*ci .. 4*ci+3
    int ri = t >> 5;       // row group:    rows 4*ri .. 4*ri+3
    float acc[4][4];
    #pragma unroll
    for (int i = 0; i < 4; i++)
        #pragma unroll
        for (int j = 0; j < 4; j++) acc[i][j] = 0.f;

    const float4* sXr = (const float4*)sX;
    const float4* sWr = (const float4*)sW;
    #pragma unroll 4
    for (int k4 = 0; k4 < 32; k4++) {
        float4 wv0 = sWr[(4 * k4 + 0) * 32 + ci];
        float4 wv1 = sWr[(4 * k4 + 1) * 32 + ci];
        float4 wv2 = sWr[(4 * k4 + 2) * 32 + ci];
        float4 wv3 = sWr[(4 * k4 + 3) * 32 + ci];
        #pragma unroll
        for (int i = 0; i < 4; i++) {
            float4 xv = sXr[(4 * ri + i) * 32 + k4];
            acc[i][0] += xv.x * wv0.x + xv.y * wv1.x + xv.z * wv2.x + xv.w * wv3.x;
            acc[i][1] += xv.x * wv0.y + xv.y * wv1.y + xv.z * wv2.y + xv.w * wv3.y;
            acc[i][2] += xv.x * wv0.z + xv.y * wv1.z + xv.z * wv2.z + xv.w * wv3.z;
            acc[i][3] += xv.x * wv0.w + xv.y * wv1.w + xv.z * wv2.w + xv.w * wv3.w;
        }
    }

    #pragma unroll
    for (int i = 0; i < 4; i++) {
        int row = row0 + 4 * ri + i;
        if (row < n) {
            float s = g_dinv[row];
            float4 o = make_float4(acc[i][0] * s, acc[i][1] * s, acc[i][2] * s, acc[i][3] * s);
            ((float4*)outA)[(size_t)row * 32 + ci] = o;  // hs for scatter
            ((float4*)outB)[(size_t)row * 32 + ci] = o;  // accumulator init (self-loop term)
        }
    }
}

// ---------------- edge scatter: B[dst] += A[src], warp per edge ----------------
__global__ void scatter_kernel(const void* __restrict__ ei, long long E,
                               const float* __restrict__ A, float* __restrict__ B) {
    long long w = (long long)blockIdx.x * (blockDim.x >> 5) + (threadIdx.x >> 5);
    int lane = threadIdx.x & 31;
    if (w >= E) return;
    int s = 0, d = 0;
    if (lane == 0) {
        s = ld_idx(ei, w);
        d = ld_idx(ei, E + w);
    }
    s = __shfl_sync(0xffffffffu, s, 0);
    d = __shfl_sync(0xffffffffu, d, 0);
    float4 v = ((const float4*)A)[(size_t)s * 32 + lane];
    float* p = B + (size_t)d * 128 + lane * 4;
    asm volatile("red.global.add.v4.f32 [%0], {%1, %2, %3, %4};"
                 :: "l"(p), "f"(v.x), "f"(v.y), "f"(v.z), "f"(v.w)
                 : "memory");
}

// ---------------- post: B = (dinv[row]*B + bias), optional relu, in place ----------------
__global__ void post_kernel(float* __restrict__ B, const float* __restrict__ bias,
                            int n, int relu) {
    long long i = (long long)blockIdx.x * blockDim.x + threadIdx.x;  // over n*32 float4s
    if (i >= (long long)n * 32) return;
    int row = (int)(i >> 5), c4 = (int)(i & 31);
    float s = g_dinv[row];
    float4 v = ((float4*)B)[i];
    float4 bb = ((const float4*)bias)[c4];
    v.x = fmaf(v.x, s, bb.x);
    v.y = fmaf(v.y, s, bb.y);
    v.z = fmaf(v.z, s, bb.z);
    v.w = fmaf(v.w, s, bb.w);
    if (relu) {
        v.x = fmaxf(v.x, 0.f); v.y = fmaxf(v.y, 0.f);
        v.z = fmaxf(v.z, 0.f); v.w = fmaxf(v.w, 0.f);
    }
    ((float4*)B)[i] = v;
}

// ---------------- decode: logits[e] = dot(Z[s], Z[d]), warp per edge ----------------
__global__ void decode_kernel(const void* __restrict__ eli, long long M,
                              const float* __restrict__ Z, float* __restrict__ out) {
    long long w = (long long)blockIdx.x * (blockDim.x >> 5) + (threadIdx.x >> 5);
    int lane = threadIdx.x & 31;
    if (w >= M) return;
    int s = 0, d = 0;
    if (lane == 0) {
        s = ld_idx(eli, w);
        d = ld_idx(eli, M + w);
    }
    s = __shfl_sync(0xffffffffu, s, 0);
    d = __shfl_sync(0xffffffffu, d, 0);
    float4 a = ((const float4*)Z)[(size_t)s * 32 + lane];
    float4 b = ((const float4*)Z)[(size_t)d * 32 + lane];
    float sum = a.x * b.x + a.y * b.y + a.z * b.z + a.w * b.w;
    #pragma unroll
    for (int o = 16; o; o >>= 1) sum += __shfl_xor_sync(0xffffffffu, sum, o);
    if (lane == 0) out[w] = sum;
}

// ---------------- launch ----------------
extern "C" void kernel_launch(void* const* d_in, const int* in_sizes, int n_in,
                              void* d_out, int out_size) {
    const float* x  = (const float*)d_in[0];
    const void*  ei = d_in[1];
    const void*  eli = d_in[2];
    const float* W1 = (const float*)d_in[3];
    const float* b1 = (const float*)d_in[4];
    const float* W2 = (const float*)d_in[5];
    const float* b2 = (const float*)d_in[6];
    float* out = (float*)d_out;

    int n = in_sizes[0] / DIM;
    long long E = in_sizes[1] / 2;
    long long M = in_sizes[2] / 2;

    float *pA = nullptr, *pB = nullptr;
    cudaGetSymbolAddress((void**)&pA, g_bufA);
    cudaGetSymbolAddress((void**)&pB, g_bufB);
    cudaFuncSetAttribute(gemm_scaled, cudaFuncAttributeMaxDynamicSharedMemorySize,
                         (int)GEMM_SMEM);

    int nb256 = (n + 255) / 256;
    int ebw   = (int)((E + 7) / 8);         // warp-per-edge blocks (8 warps/block)
    int mbw   = (int)((M + 7) / 8);
    int fb    = (int)(((long long)n * 32 + 255) / 256);

    detect_kernel<<<1, 32>>>((const unsigned int*)ei);
    deg_init<<<nb256, 256>>>(n);
    deg_count<<<(int)((E + 255) / 256), 256>>>(ei, E);
    dinv_kernel<<<nb256, 256>>>(n);

    // Layer 1
    gemm_scaled<<<(n + 31) / 32, 256, GEMM_SMEM>>>(x, W1, pA, pB, n);
    scatter_kernel<<<ebw, 256>>>(ei, E, pA, pB);
    post_kernel<<<fb, 256>>>(pB, b1, n, 1);

    // Layer 2 (gemm reads/writes pB per-row in place; also emits hs into pA)
    gemm_scaled<<<(n + 31) / 32, 256, GEMM_SMEM>>>(pB, W2, pA, pB, n);
    scatter_kernel<<<ebw, 256>>>(ei, E, pA, pB);
    post_kernel<<<fb, 256>>>(pB, b2, n, 0);

    // Decode
    decode_kernel<<<mbw, 256>>>(eli, M, pB, out);
}

// round 2
// speedup vs baseline: 1.7090x; 1.7090x over previous
#include <cuda_runtime.h>
#include <math.h>

#define DIM 128
#define NMAX 100000
#define EMAX 2000000

// Scratch (allocation-free rule: __device__ globals)
__device__ float g_bufA[(size_t)NMAX * DIM];   // hs (messages, pre-scaled by dinv[src])
__device__ float g_bufB[(size_t)NMAX * DIM];   // activations
__device__ int   g_deg[NMAX];                  // edge in-degree (no self loop)
__device__ float g_dinv[NMAX];
__device__ int   g_rowptr[NMAX + 1];
__device__ int   g_cursor[NMAX];
__device__ int   g_csrc[EMAX];
__device__ int   g_bsum[512];
__device__ int   g_is64;

// ---------------- index dtype detection + loader ----------------
__global__ void detect_kernel(const unsigned int* __restrict__ p) {
    if (threadIdx.x == 0 && blockIdx.x == 0) {
        int is64 = 1;
        #pragma unroll
        for (int i = 0; i < 64; i++)
            if (p[2 * i + 1] != 0u) is64 = 0;
        g_is64 = is64;
    }
}

__device__ __forceinline__ int ld_idx(const void* p, long long i) {
    if (g_is64) return (int)((const long long*)p)[i];
    return ((const int*)p)[i];
}

// ---------------- degree / norm ----------------
__global__ void deg_init(int n) {
    int i = blockIdx.x * blockDim.x + threadIdx.x;
    if (i < n) g_deg[i] = 0;
}

__global__ void deg_count(const void* __restrict__ ei, long long E) {
    long long i = (long long)blockIdx.x * blockDim.x + threadIdx.x;
    if (i < E) atomicAdd(&g_deg[ld_idx(ei, E + i)], 1);
}

__global__ void dinv_kernel(int n) {
    int i = blockIdx.x * blockDim.x + threadIdx.x;
    if (i < n) g_dinv[i] = rsqrtf((float)(g_deg[i] + 1));  // +1 self loop
}

// ---------------- 3-phase exclusive prefix scan of g_deg -> g_rowptr ----------------
__global__ void scan_partial(int n) {  // 256 threads/block, one elem/thread
    int i = blockIdx.x * 256 + threadIdx.x;
    int v = (i < n) ? g_deg[i] : 0;
    #pragma unroll
    for (int o = 16; o; o >>= 1) v += __shfl_down_sync(0xffffffffu, v, o);
    __shared__ int ws[8];
    if ((threadIdx.x & 31) == 0) ws[threadIdx.x >> 5] = v;
    __syncthreads();
    if (threadIdx.x == 0) {
        int s = 0;
        #pragma unroll
        for (int k = 0; k < 8; k++) s += ws[k];
        g_bsum[blockIdx.x] = s;
    }
}

__global__ void scan_top(int nb) {  // 1 block, 512 threads, nb <= 512
    __shared__ int sh[512];
    int t = threadIdx.x;
    int v = (t < nb) ? g_bsum[t] : 0;
    sh[t] = v;
    __syncthreads();
    #pragma unroll
    for (int o = 1; o < 512; o <<= 1) {
        int u = (t >= o) ? sh[t - o] : 0;
        __syncthreads();
        sh[t] += u;
        __syncthreads();
    }
    if (t < nb) g_bsum[t] = sh[t] - v;  // exclusive
}

__global__ void scan_final(int n, long long E) {  // 256 threads/block
    int t = threadIdx.x, lane = t & 31, wid = t >> 5;
    int i = blockIdx.x * 256 + t;
    int v = (i < n) ? g_deg[i] : 0;
    int incl = v;
    #pragma unroll
    for (int o = 1; o < 32; o <<= 1) {
        int u = __shfl_up_sync(0xffffffffu, incl, o);
        if (lane >= o) incl += u;
    }
    __shared__ int ws[8], wso[8];
    if (lane == 31) ws[wid] = incl;
    __syncthreads();
    if (t == 0) {
        int s = 0;
        #pragma unroll
        for (int k = 0; k < 8; k++) { wso[k] = s; s += ws[k]; }
    }
    __syncthreads();
    int excl = incl - v + wso[wid] + g_bsum[blockIdx.x];
    if (i < n) { g_rowptr[i] = excl; g_cursor[i] = excl; }
    if (i == n - 1) g_rowptr[n] = (int)E;
}

__global__ void fill_kernel(const void* __restrict__ ei, long long E) {
    long long i = (long long)blockIdx.x * blockDim.x + threadIdx.x;
    if (i >= E) return;
    int s = ld_idx(ei, i);
    int d = ld_idx(ei, E + i);
    int pos = atomicAdd(&g_cursor[d], 1);
    g_csrc[pos] = s;
}

// ---------------- fp32 GEMM: out = (X @ W) * dinv[row] ----------------
#define GEMM_SMEM ((DIM * DIM + 32 * DIM) * sizeof(float))

__global__ void gemm_scaled(const float* __restrict__ X, const float* __restrict__ W,
                            float* __restrict__ outA, int n) {
    extern __shared__ float sm[];
    float* sW = sm;             // [128][128]
    float* sX = sm + DIM * DIM; // [32][128]
    int t = threadIdx.x;

    const float4* W4 = (const float4*)W;
    float4* sW4 = (float4*)sW;
    #pragma unroll
    for (int i = 0; i < 16; i++) sW4[t + 256 * i] = W4[t + 256 * i];

    int row0 = blockIdx.x * 32;
    const float4* X4 = (const float4*)X;
    float4* sX4 = (float4*)sX;
    #pragma unroll
    for (int i = 0; i < 4; i++) {
        int q = t + 256 * i;
        int r = q >> 5, c4 = q & 31;
        int row = row0 + r;
        float4 f = (row < n) ? X4[(size_t)row * 32 + c4] : make_float4(0.f, 0.f, 0.f, 0.f);
        sX4[r * 32 + c4] = f;
    }
    __syncthreads();

    int ci = t & 31;
    int ri = t >> 5;
    float acc[4][4];
    #pragma unroll
    for (int i = 0; i < 4; i++)
        #pragma unroll
        for (int j = 0; j < 4; j++) acc[i][j] = 0.f;

    const float4* sXr = (const float4*)sX;
    const float4* sWr = (const float4*)sW;
    #pragma unroll 4
    for (int k4 = 0; k4 < 32; k4++) {
        float4 wv0 = sWr[(4 * k4 + 0) * 32 + ci];
        float4 wv1 = sWr[(4 * k4 + 1) * 32 + ci];
        float4 wv2 = sWr[(4 * k4 + 2) * 32 + ci];
        float4 wv3 = sWr[(4 * k4 + 3) * 32 + ci];
        #pragma unroll
        for (int i = 0; i < 4; i++) {
            float4 xv = sXr[(4 * ri + i) * 32 + k4];
            acc[i][0] += xv.x * wv0.x + xv.y * wv1.x + xv.z * wv2.x + xv.w * wv3.x;
            acc[i][1] += xv.x * wv0.y + xv.y * wv1.y + xv.z * wv2.y + xv.w * wv3.y;
            acc[i][2] += xv.x * wv0.z + xv.y * wv1.z + xv.z * wv2.z + xv.w * wv3.z;
            acc[i][3] += xv.x * wv0.w + xv.y * wv1.w + xv.z * wv2.w + xv.w * wv3.w;
        }
    }

    #pragma unroll
    for (int i = 0; i < 4; i++) {
        int row = row0 + 4 * ri + i;
        if (row < n) {
            float s = g_dinv[row];
            ((float4*)outA)[(size_t)row * 32 + ci] =
                make_float4(acc[i][0] * s, acc[i][1] * s, acc[i][2] * s, acc[i][3] * s);
        }
    }
}

// ---------------- CSR gather: B[d] = relu?(dinv[d]*(hs[d] + sum_nbrs hs[s]) + bias) ----------------
__global__ void gather_kernel(const float* __restrict__ A, float* __restrict__ B,
                              const float* __restrict__ bias, int n, int relu) {
    int node = blockIdx.x * (blockDim.x >> 5) + (threadIdx.x >> 5);
    int lane = threadIdx.x & 31;
    if (node >= n) return;
    int beg = g_rowptr[node], end = g_rowptr[node + 1];
    const float4* A4 = (const float4*)A;

    float4 acc = A4[(size_t)node * 32 + lane];  // self-loop term

    for (int j0 = beg; j0 < end; j0 += 32) {
        int m = min(32, end - j0);
        int idx = (lane < m) ? g_csrc[j0 + lane] : 0;
        int k = 0;
        for (; k + 4 <= m; k += 4) {
            int s0 = __shfl_sync(0xffffffffu, idx, k);
            int s1 = __shfl_sync(0xffffffffu, idx, k + 1);
            int s2 = __shfl_sync(0xffffffffu, idx, k + 2);
            int s3 = __shfl_sync(0xffffffffu, idx, k + 3);
            float4 v0 = A4[(size_t)s0 * 32 + lane];
            float4 v1 = A4[(size_t)s1 * 32 + lane];
            float4 v2 = A4[(size_t)s2 * 32 + lane];
            float4 v3 = A4[(size_t)s3 * 32 + lane];
            acc.x += (v0.x + v1.x) + (v2.x + v3.x);
            acc.y += (v0.y + v1.y) + (v2.y + v3.y);
            acc.z += (v0.z + v1.z) + (v2.z + v3.z);
            acc.w += (v0.w + v1.w) + (v2.w + v3.w);
        }
        for (; k < m; k++) {
            int s = __shfl_sync(0xffffffffu, idx, k);
            float4 v = A4[(size_t)s * 32 + lane];
            acc.x += v.x; acc.y += v.y; acc.z += v.z; acc.w += v.w;
        }
    }

    float sc = g_dinv[node];
    float4 bb = ((const float4*)bias)[lane];
    float4 o;
    o.x = fmaf(acc.x, sc, bb.x);
    o.y = fmaf(acc.y, sc, bb.y);
    o.z = fmaf(acc.z, sc, bb.z);
    o.w = fmaf(acc.w, sc, bb.w);
    if (relu) {
        o.x = fmaxf(o.x, 0.f); o.y = fmaxf(o.y, 0.f);
        o.z = fmaxf(o.z, 0.f); o.w = fmaxf(o.w, 0.f);
    }
    ((float4*)B)[(size_t)node * 32 + lane] = o;
}

// ---------------- decode: logits[e] = dot(Z[s], Z[d]), warp per edge ----------------
__global__ void decode_kernel(const void* __restrict__ eli, long long M,
                              const float* __restrict__ Z, float* __restrict__ out) {
    long long w = (long long)blockIdx.x * (blockDim.x >> 5) + (threadIdx.x >> 5);
    int lane = threadIdx.x & 31;
    if (w >= M) return;
    int s = 0, d = 0;
    if (lane == 0) {
        s = ld_idx(eli, w);
        d = ld_idx(eli, M + w);
    }
    s = __shfl_sync(0xffffffffu, s, 0);
    d = __shfl_sync(0xffffffffu, d, 0);
    float4 a = ((const float4*)Z)[(size_t)s * 32 + lane];
    float4 b = ((const float4*)Z)[(size_t)d * 32 + lane];
    float sum = a.x * b.x + a.y * b.y + a.z * b.z + a.w * b.w;
    #pragma unroll
    for (int o = 16; o; o >>= 1) sum += __shfl_xor_sync(0xffffffffu, sum, o);
    if (lane == 0) out[w] = sum;
}

// ---------------- launch ----------------
extern "C" void kernel_launch(void* const* d_in, const int* in_sizes, int n_in,
                              void* d_out, int out_size) {
    const float* x   = (const float*)d_in[0];
    const void*  ei  = d_in[1];
    const void*  eli = d_in[2];
    const float* W1  = (const float*)d_in[3];
    const float* b1  = (const float*)d_in[4];
    const float* W2  = (const float*)d_in[5];
    const float* b2  = (const float*)d_in[6];
    float* out = (float*)d_out;

    int n = in_sizes[0] / DIM;
    long long E = in_sizes[1] / 2;
    long long M = in_sizes[2] / 2;

    float *pA = nullptr, *pB = nullptr;
    cudaGetSymbolAddress((void**)&pA, g_bufA);
    cudaGetSymbolAddress((void**)&pB, g_bufB);
    cudaFuncSetAttribute(gemm_scaled, cudaFuncAttributeMaxDynamicSharedMemorySize,
                         (int)GEMM_SMEM);

    int nb256 = (n + 255) / 256;
    int eb    = (int)((E + 255) / 256);
    int mbw   = (int)((M + 7) / 8);
    int gbw   = (n + 7) / 8;  // gather: 8 warps/block, warp per node

    detect_kernel<<<1, 32>>>((const unsigned int*)ei);
    deg_init<<<nb256, 256>>>(n);
    deg_count<<<eb, 256>>>(ei, E);
    dinv_kernel<<<nb256, 256>>>(n);

    // CSR build
    scan_partial<<<nb256, 256>>>(n);
    scan_top<<<1, 512>>>(nb256);
    scan_final<<<nb256, 256>>>(n, E);
    fill_kernel<<<eb, 256>>>(ei, E);

    // Layer 1
    gemm_scaled<<<(n + 31) / 32, 256, GEMM_SMEM>>>(x, W1, pA, n);
    gather_kernel<<<gbw, 256>>>(pA, pB, b1, n, 1);

    // Layer 2
    gemm_scaled<<<(n + 31) / 32, 256, GEMM_SMEM>>>(pB, W2, pA, n);
    gather_kernel<<<gbw, 256>>>(pA, pB, b2, n, 0);

    // Decode
    decode_kernel<<<mbw, 256>>>(eli, M, pB, out);
}

// round 4
// speedup vs baseline: 2.1044x; 1.2314x over previous
#include <cuda_runtime.h>
#include <cuda_bf16.h>
#include <math.h>
#include <stdint.h>

#define DIM 128
#define NMAX 100000
#define EMAX 2000000

// Scratch (allocation-free rule: __device__ globals)
__device__ float    g_bufA[(size_t)NMAX * DIM];   // hs messages (scaled by dinv[src])
__device__ float    g_bufB[(size_t)NMAX * DIM];   // activations
__device__ int      g_deg[NMAX];
__device__ float    g_dinv[NMAX];
__device__ int      g_rowptr[NMAX + 1];
__device__ int      g_cursor[NMAX];
__device__ int      g_csrc[EMAX];
__device__ int      g_bsum[512];
__device__ int      g_is64;
__device__ uint32_t g_Wimg[2][2][8192];           // [layer][hi/lo][swizzled bf16x2 image]

// ======================= helpers =======================
__device__ __forceinline__ uint32_t smem_u32(const void* p) {
    uint32_t a;
    asm("{ .reg .u64 t; cvta.to.shared.u64 t, %1; cvt.u32.u64 %0, t; }" : "=r"(a) : "l"(p));
    return a;
}

// Blocked SW128 atom layout for a [rows=128, K=128] bf16 tile.
// atom = 8 rows x 64 bf16 (1024B); atom_offset = atom_row + atom_col*16.
__host__ __device__ __forceinline__ uint32_t blk_off(int row, int col /*bf16 idx*/) {
    uint32_t off = (uint32_t)((row >> 3) + (col >> 6) * 16) * 1024u
                 + (uint32_t)(row & 7) * 128u + (uint32_t)(col & 63) * 2u;
    return off ^ ((off >> 3) & 0x70u);
}

__device__ __forceinline__ void ldsm4(uint32_t* r, uint32_t addr) {
    asm volatile("ldmatrix.sync.aligned.m8n8.x4.shared.b16 {%0,%1,%2,%3}, [%4];"
                 : "=r"(r[0]), "=r"(r[1]), "=r"(r[2]), "=r"(r[3]) : "r"(addr));
}

__device__ __forceinline__ void mma_bf16(float* d, const uint32_t* a,
                                         uint32_t b0, uint32_t b1) {
    asm volatile(
        "mma.sync.aligned.m16n8k16.row.col.f32.bf16.bf16.f32 "
        "{%0,%1,%2,%3}, {%4,%5,%6,%7}, {%8,%9}, {%0,%1,%2,%3};"
        : "+f"(d[0]), "+f"(d[1]), "+f"(d[2]), "+f"(d[3])
        : "r"(a[0]), "r"(a[1]), "r"(a[2]), "r"(a[3]), "r"(b0), "r"(b1));
}

// ======================= index dtype detection =======================
__global__ void detect_kernel(const unsigned int* __restrict__ p) {
    if (threadIdx.x == 0 && blockIdx.x == 0) {
        int is64 = 1;
        #pragma unroll
        for (int i = 0; i < 64; i++)
            if (p[2 * i + 1] != 0u) is64 = 0;
        g_is64 = is64;
    }
}

__device__ __forceinline__ int ld_idx(const void* p, long long i) {
    if (g_is64) return (int)((const long long*)p)[i];
    return ((const int*)p)[i];
}

// ======================= degree / norm =======================
__global__ void deg_init(int n) {
    int i = blockIdx.x * blockDim.x + threadIdx.x;
    if (i < n) g_deg[i] = 0;
}

__global__ void deg_count(const void* __restrict__ ei, long long E) {
    long long i = (long long)blockIdx.x * blockDim.x + threadIdx.x;
    if (i < E) atomicAdd(&g_deg[ld_idx(ei, E + i)], 1);
}

__global__ void dinv_kernel(int n) {
    int i = blockIdx.x * blockDim.x + threadIdx.x;
    if (i < n) g_dinv[i] = rsqrtf((float)(g_deg[i] + 1));
}

// ======================= prefix scan -> CSR =======================
__global__ void scan_partial(int n) {
    int i = blockIdx.x * 256 + threadIdx.x;
    int v = (i < n) ? g_deg[i] : 0;
    #pragma unroll
    for (int o = 16; o; o >>= 1) v += __shfl_down_sync(0xffffffffu, v, o);
    __shared__ int ws[8];
    if ((threadIdx.x & 31) == 0) ws[threadIdx.x >> 5] = v;
    __syncthreads();
    if (threadIdx.x == 0) {
        int s = 0;
        #pragma unroll
        for (int k = 0; k < 8; k++) s += ws[k];
        g_bsum[blockIdx.x] = s;
    }
}

__global__ void scan_top(int nb) {
    __shared__ int sh[512];
    int t = threadIdx.x;
    int v = (t < nb) ? g_bsum[t] : 0;
    sh[t] = v;
    __syncthreads();
    #pragma unroll
    for (int o = 1; o < 512; o <<= 1) {
        int u = (t >= o) ? sh[t - o] : 0;
        __syncthreads();
        sh[t] += u;
        __syncthreads();
    }
    if (t < nb) g_bsum[t] = sh[t] - v;
}

__global__ void scan_final(int n, long long E) {
    int t = threadIdx.x, lane = t & 31, wid = t >> 5;
    int i = blockIdx.x * 256 + t;
    int v = (i < n) ? g_deg[i] : 0;
    int incl = v;
    #pragma unroll
    for (int o = 1; o < 32; o <<= 1) {
        int u = __shfl_up_sync(0xffffffffu, incl, o);
        if (lane >= o) incl += u;
    }
    __shared__ int ws[8], wso[8];
    if (lane == 31) ws[wid] = incl;
    __syncthreads();
    if (t == 0) {
        int s = 0;
        #pragma unroll
        for (int k = 0; k < 8; k++) { wso[k] = s; s += ws[k]; }
    }
    __syncthreads();
    int excl = incl - v + wso[wid] + g_bsum[blockIdx.x];
    if (i < n) { g_rowptr[i] = excl; g_cursor[i] = excl; }
    if (i == n - 1) g_rowptr[n] = (int)E;
}

__global__ void fill_kernel(const void* __restrict__ ei, long long E) {
    long long i = (long long)blockIdx.x * blockDim.x + threadIdx.x;
    if (i >= E) return;
    int s = ld_idx(ei, i);
    int d = ld_idx(ei, E + i);
    int pos = atomicAdd(&g_cursor[d], 1);
    g_csrc[pos] = s;
}

// ======================= W split+transpose into swizzled images =======================
// B tile for mma: rows = N (out-feature), K contiguous. W is [K,N] row-major.
__global__ void wprep(const float* __restrict__ W1, const float* __restrict__ W2,
                      uint32_t* __restrict__ img) {
    int i = blockIdx.x * 256 + threadIdx.x;      // 2 layers * 128 n * 64 k2
    if (i >= 16384) return;
    int l = i >> 13, rem = i & 8191;
    int nrow = rem >> 6, k2 = rem & 63;
    const float* W = l ? W2 : W1;
    float x0 = W[(2 * k2) * 128 + nrow];
    float x1 = W[(2 * k2 + 1) * 128 + nrow];
    __nv_bfloat16 h0 = __float2bfloat16(x0);
    __nv_bfloat16 h1 = __float2bfloat16(x1);
    __nv_bfloat16 l0 = __float2bfloat16(x0 - __bfloat162float(h0));
    __nv_bfloat16 l1 = __float2bfloat16(x1 - __bfloat162float(h1));
    uint32_t hw = ((uint32_t)__bfloat16_as_ushort(h1) << 16) | __bfloat16_as_ushort(h0);
    uint32_t lw = ((uint32_t)__bfloat16_as_ushort(l1) << 16) | __bfloat16_as_ushort(l0);
    uint32_t widx = blk_off(nrow, 2 * k2) >> 2;
    img[l * 16384 + widx] = hw;
    img[l * 16384 + 8192 + widx] = lw;
}

// ======================= HMMA GEMM: outA = (X @ W) * dinv[row] =======================
// 2-way bf16 split of X and W; 3 passes (hi*hi + hi*lo + lo*hi), fp32 register accum.
#define SM_AHI 0
#define SM_ALO 32768
#define SM_BHI 65536
#define SM_BLO 98304
#define GEMM_SMEM 131072

__global__ void __launch_bounds__(256, 1)
gemm_tc(const float* __restrict__ X, const uint32_t* __restrict__ Wimg,
        float* __restrict__ outA, int n) {
    extern __shared__ char sm[];
    uint32_t smem_base = smem_u32(sm);
    int t = threadIdx.x;
    int w = t >> 5, lane = t & 31;
    int row0 = blockIdx.x * 128;

    // ---- load X tile, split into bf16 hi/lo, write blocked+swizzled SMEM ----
    {
        int lrow = t >> 1;          // 0..127
        int kh = t & 1;             // which 64-col half
        int row = row0 + lrow;
        const float4* X4 = (const float4*)X;
        #pragma unroll 4
        for (int i = 0; i < 16; i++) {
            float4 v = (row < n) ? X4[(size_t)row * 32 + kh * 16 + i]
                                 : make_float4(0.f, 0.f, 0.f, 0.f);
            int k = kh * 64 + i * 4;
            __nv_bfloat16 hx = __float2bfloat16(v.x), hy = __float2bfloat16(v.y);
            __nv_bfloat16 hz = __float2bfloat16(v.z), hw_ = __float2bfloat16(v.w);
            __nv_bfloat16 lx = __float2bfloat16(v.x - __bfloat162float(hx));
            __nv_bfloat16 ly = __float2bfloat16(v.y - __bfloat162float(hy));
            __nv_bfloat16 lz = __float2bfloat16(v.z - __bfloat162float(hz));
            __nv_bfloat16 lw = __float2bfloat16(v.w - __bfloat162float(hw_));
            uint32_t hi0 = ((uint32_t)__bfloat16_as_ushort(hy) << 16) | __bfloat16_as_ushort(hx);
            uint32_t hi1 = ((uint32_t)__bfloat16_as_ushort(hw_) << 16) | __bfloat16_as_ushort(hz);
            uint32_t lo0 = ((uint32_t)__bfloat16_as_ushort(ly) << 16) | __bfloat16_as_ushort(lx);
            uint32_t lo1 = ((uint32_t)__bfloat16_as_ushort(lw) << 16) | __bfloat16_as_ushort(lz);
            uint32_t o0 = blk_off(lrow, k), o1 = blk_off(lrow, k + 2);
            *(uint32_t*)(sm + SM_AHI + o0) = hi0;
            *(uint32_t*)(sm + SM_AHI + o1) = hi1;
            *(uint32_t*)(sm + SM_ALO + o0) = lo0;
            *(uint32_t*)(sm + SM_ALO + o1) = lo1;
        }
    }
    // ---- copy pre-swizzled W images ----
    {
        const uint4* sh = (const uint4*)Wimg;          // hi: 2048 uint4
        const uint4* sl = (const uint4*)(Wimg + 8192); // lo
        uint4* dh = (uint4*)(sm + SM_BHI);
        uint4* dl = (uint4*)(sm + SM_BLO);
        #pragma unroll
        for (int i = 0; i < 8; i++) {
            dh[t + 256 * i] = sh[t + 256 * i];
            dl[t + 256 * i] = sl[t + 256 * i];
        }
    }
    __syncthreads();

    // ---- warp tile: rows mwarp..+32, cols nwarp..+64 ----
    int mwarp = (w & 3) * 32;
    int nwarp = (w >> 2) * 64;

    float acc[2][8][4];
    #pragma unroll
    for (int mi = 0; mi < 2; mi++)
        #pragma unroll
        for (int nj = 0; nj < 8; nj++)
            #pragma unroll
            for (int q = 0; q < 4; q++) acc[mi][nj][q] = 0.f;

    // ldmatrix per-thread address components
    int a_row = mwarp + (lane & 15);
    int a_kof = (lane >> 4) << 3;
    int b_row = nwarp + (lane & 7) + ((lane >> 4) << 3);
    int b_kof = (lane & 8);

    const uint32_t Aoff[3] = { SM_AHI, SM_AHI, SM_ALO };
    const uint32_t Boff[3] = { SM_BHI, SM_BLO, SM_BHI };

    #pragma unroll
    for (int p = 0; p < 3; p++) {
        uint32_t Abase = smem_base + Aoff[p];
        uint32_t Bbase = smem_base + Boff[p];
        #pragma unroll
        for (int ks = 0; ks < 8; ks++) {
            int k0 = ks * 16;
            uint32_t a[2][4];
            ldsm4(a[0], Abase + blk_off(a_row,      k0 + a_kof));
            ldsm4(a[1], Abase + blk_off(a_row + 16, k0 + a_kof));
            uint32_t b[4][4];
            #pragma unroll
            for (int g = 0; g < 4; g++)
                ldsm4(b[g], Bbase + blk_off(b_row + g * 16, k0 + b_kof));
            #pragma unroll
            for (int mi = 0; mi < 2; mi++)
                #pragma unroll
                for (int g = 0; g < 4; g++) {
                    mma_bf16(acc[mi][2 * g],     a[mi], b[g][0], b[g][1]);
                    mma_bf16(acc[mi][2 * g + 1], a[mi], b[g][2], b[g][3]);
                }
        }
    }

    // ---- epilogue: scale by dinv[row], store float2 ----
    {
        int g = lane >> 2, i2 = lane & 3;
        #pragma unroll
        for (int mi = 0; mi < 2; mi++) {
            int r0 = row0 + mwarp + mi * 16 + g;
            int r1 = r0 + 8;
            float s0 = (r0 < n) ? g_dinv[r0] : 0.f;
            float s1 = (r1 < n) ? g_dinv[r1] : 0.f;
            #pragma unroll
            for (int nj = 0; nj < 8; nj++) {
                int c = nwarp + nj * 8 + 2 * i2;
                if (r0 < n)
                    *(float2*)(outA + (size_t)r0 * 128 + c) =
                        make_float2(acc[mi][nj][0] * s0, acc[mi][nj][1] * s0);
                if (r1 < n)
                    *(float2*)(outA + (size_t)r1 * 128 + c) =
                        make_float2(acc[mi][nj][2] * s1, acc[mi][nj][3] * s1);
            }
        }
    }
}

// ======================= CSR gather =======================
__global__ void gather_kernel(const float* __restrict__ A, float* __restrict__ B,
                              const float* __restrict__ bias, int n, int relu) {
    int node = blockIdx.x * (blockDim.x >> 5) + (threadIdx.x >> 5);
    int lane = threadIdx.x & 31;
    if (node >= n) return;
    int beg = g_rowptr[node], end = g_rowptr[node + 1];
    const float4* A4 = (const float4*)A;

    float4 acc = A4[(size_t)node * 32 + lane];  // self-loop term

    for (int j0 = beg; j0 < end; j0 += 32) {
        int m = min(32, end - j0);
        int idx = (lane < m) ? g_csrc[j0 + lane] : 0;
        int k = 0;
        for (; k + 4 <= m; k += 4) {
            int s0 = __shfl_sync(0xffffffffu, idx, k);
            int s1 = __shfl_sync(0xffffffffu, idx, k + 1);
            int s2 = __shfl_sync(0xffffffffu, idx, k + 2);
            int s3 = __shfl_sync(0xffffffffu, idx, k + 3);
            float4 v0 = A4[(size_t)s0 * 32 + lane];
            float4 v1 = A4[(size_t)s1 * 32 + lane];
            float4 v2 = A4[(size_t)s2 * 32 + lane];
            float4 v3 = A4[(size_t)s3 * 32 + lane];
            acc.x += (v0.x + v1.x) + (v2.x + v3.x);
            acc.y += (v0.y + v1.y) + (v2.y + v3.y);
            acc.z += (v0.z + v1.z) + (v2.z + v3.z);
            acc.w += (v0.w + v1.w) + (v2.w + v3.w);
        }
        for (; k < m; k++) {
            int s = __shfl_sync(0xffffffffu, idx, k);
            float4 v = A4[(size_t)s * 32 + lane];
            acc.x += v.x; acc.y += v.y; acc.z += v.z; acc.w += v.w;
        }
    }

    float sc = g_dinv[node];
    float4 bb = ((const float4*)bias)[lane];
    float4 o;
    o.x = fmaf(acc.x, sc, bb.x);
    o.y = fmaf(acc.y, sc, bb.y);
    o.z = fmaf(acc.z, sc, bb.z);
    o.w = fmaf(acc.w, sc, bb.w);
    if (relu) {
        o.x = fmaxf(o.x, 0.f); o.y = fmaxf(o.y, 0.f);
        o.z = fmaxf(o.z, 0.f); o.w = fmaxf(o.w, 0.f);
    }
    ((float4*)B)[(size_t)node * 32 + lane] = o;
}

// ======================= decode =======================
__global__ void decode_kernel(const void* __restrict__ eli, long long M,
                              const float* __restrict__ Z, float* __restrict__ out) {
    long long w = (long long)blockIdx.x * (blockDim.x >> 5) + (threadIdx.x >> 5);
    int lane = threadIdx.x & 31;
    if (w >= M) return;
    int s = 0, d = 0;
    if (lane == 0) {
        s = ld_idx(eli, w);
        d = ld_idx(eli, M + w);
    }
    s = __shfl_sync(0xffffffffu, s, 0);
    d = __shfl_sync(0xffffffffu, d, 0);
    float4 a = ((const float4*)Z)[(size_t)s * 32 + lane];
    float4 b = ((const float4*)Z)[(size_t)d * 32 + lane];
    float sum = a.x * b.x + a.y * b.y + a.z * b.z + a.w * b.w;
    #pragma unroll
    for (int o = 16; o; o >>= 1) sum += __shfl_xor_sync(0xffffffffu, sum, o);
    if (lane == 0) out[w] = sum;
}

// ======================= launch =======================
extern "C" void kernel_launch(void* const* d_in, const int* in_sizes, int n_in,
                              void* d_out, int out_size) {
    const float* x   = (const float*)d_in[0];
    const void*  ei  = d_in[1];
    const void*  eli = d_in[2];
    const float* W1  = (const float*)d_in[3];
    const float* b1  = (const float*)d_in[4];
    const float* W2  = (const float*)d_in[5];
    const float* b2  = (const float*)d_in[6];
    float* out = (float*)d_out;

    int n = in_sizes[0] / DIM;
    long long E = in_sizes[1] / 2;
    long long M = in_sizes[2] / 2;

    float *pA = nullptr, *pB = nullptr;
    uint32_t* pW = nullptr;
    cudaGetSymbolAddress((void**)&pA, g_bufA);
    cudaGetSymbolAddress((void**)&pB, g_bufB);
    cudaGetSymbolAddress((void**)&pW, g_Wimg);
    cudaFuncSetAttribute(gemm_tc, cudaFuncAttributeMaxDynamicSharedMemorySize, GEMM_SMEM);

    int nb256 = (n + 255) / 256;
    int eb    = (int)((E + 255) / 256);
    int mbw   = (int)((M + 7) / 8);
    int gbw   = (n + 7) / 8;
    int gemmb = (n + 127) / 128;

    detect_kernel<<<1, 32>>>((const unsigned int*)ei);
    deg_init<<<nb256, 256>>>(n);
    deg_count<<<eb, 256>>>(ei, E);
    dinv_kernel<<<nb256, 256>>>(n);

    scan_partial<<<nb256, 256>>>(n);
    scan_top<<<1, 512>>>(nb256);
    scan_final<<<nb256, 256>>>(n, E);
    fill_kernel<<<eb, 256>>>(ei, E);

    wprep<<<64, 256>>>(W1, W2, pW);

    // Layer 1
    gemm_tc<<<gemmb, 256, GEMM_SMEM>>>(x, pW, pA, n);
    gather_kernel<<<gbw, 256>>>(pA, pB, b1, n, 1);

    // Layer 2
    gemm_tc<<<gemmb, 256, GEMM_SMEM>>>(pB, pW + 16384, pA, n);
    gather_kernel<<<gbw, 256>>>(pA, pB, b2, n, 0);

    // Decode
    decode_kernel<<<mbw, 256>>>(eli, M, pB, out);
}

// round 5
// speedup vs baseline: 2.1360x; 1.0150x over previous
#include <cuda_runtime.h>
#include <cuda_bf16.h>
#include <math.h>
#include <stdint.h>

#define DIM 128
#define NMAX 100000
#define EMAX 2000000

// Scratch (allocation-free rule: __device__ globals)
__device__ float    g_bufA[(size_t)NMAX * DIM];   // h (unscaled GEMM output)
__device__ float    g_bufB[(size_t)NMAX * DIM];   // activations
__device__ int      g_deg[NMAX];
__device__ float    g_dinv[NMAX];
__device__ int      g_rowptr[NMAX + 1];
__device__ int      g_cursor[NMAX];
__device__ int      g_csrc[EMAX];
__device__ int      g_bsum[512];
__device__ int      g_is64;
__device__ uint32_t g_Wimg[2][2][8192];           // [layer][hi/lo][swizzled bf16x2 image]

// ======================= helpers =======================
__device__ __forceinline__ uint32_t smem_u32(const void* p) {
    uint32_t a;
    asm("{ .reg .u64 t; cvta.to.shared.u64 t, %1; cvt.u32.u64 %0, t; }" : "=r"(a) : "l"(p));
    return a;
}

// Blocked SW128 atom layout for a [rows=128, K=128] bf16 tile.
__host__ __device__ __forceinline__ uint32_t blk_off(int row, int col /*bf16 idx*/) {
    uint32_t off = (uint32_t)((row >> 3) + (col >> 6) * 16) * 1024u
                 + (uint32_t)(row & 7) * 128u + (uint32_t)(col & 63) * 2u;
    return off ^ ((off >> 3) & 0x70u);
}

__device__ __forceinline__ void ldsm4(uint32_t* r, uint32_t addr) {
    asm volatile("ldmatrix.sync.aligned.m8n8.x4.shared.b16 {%0,%1,%2,%3}, [%4];"
                 : "=r"(r[0]), "=r"(r[1]), "=r"(r[2]), "=r"(r[3]) : "r"(addr));
}

__device__ __forceinline__ void mma_bf16(float* d, const uint32_t* a,
                                         uint32_t b0, uint32_t b1) {
    asm volatile(
        "mma.sync.aligned.m16n8k16.row.col.f32.bf16.bf16.f32 "
        "{%0,%1,%2,%3}, {%4,%5,%6,%7}, {%8,%9}, {%0,%1,%2,%3};"
        : "+f"(d[0]), "+f"(d[1]), "+f"(d[2]), "+f"(d[3])
        : "r"(a[0]), "r"(a[1]), "r"(a[2]), "r"(a[3]), "r"(b0), "r"(b1));
}

// ======================= index dtype detection =======================
__global__ void detect_kernel(const unsigned int* __restrict__ p) {
    if (threadIdx.x == 0 && blockIdx.x == 0) {
        int is64 = 1;
        #pragma unroll
        for (int i = 0; i < 64; i++)
            if (p[2 * i + 1] != 0u) is64 = 0;
        g_is64 = is64;
    }
}

__device__ __forceinline__ int ld_idx(const void* p, long long i) {
    if (g_is64) return (int)((const long long*)p)[i];
    return ((const int*)p)[i];
}

// ======================= degree =======================
__global__ void deg_count(const void* __restrict__ ei, long long E) {
    long long i = (long long)blockIdx.x * blockDim.x + threadIdx.x;
    if (i < E) atomicAdd(&g_deg[ld_idx(ei, E + i)], 1);
}

// ======================= prefix scan -> CSR (+ dinv fused) =======================
__global__ void scan_partial(int n) {
    int i = blockIdx.x * 256 + threadIdx.x;
    int v = (i < n) ? g_deg[i] : 0;
    if (i < n) g_dinv[i] = rsqrtf((float)(v + 1));  // fused dinv (+1 self loop)
    int s = v;
    #pragma unroll
    for (int o = 16; o; o >>= 1) s += __shfl_down_sync(0xffffffffu, s, o);
    __shared__ int ws[8];
    if ((threadIdx.x & 31) == 0) ws[threadIdx.x >> 5] = s;
    __syncthreads();
    if (threadIdx.x == 0) {
        int t = 0;
        #pragma unroll
        for (int k = 0; k < 8; k++) t += ws[k];
        g_bsum[blockIdx.x] = t;
    }
}

__global__ void scan_top(int nb) {
    __shared__ int sh[512];
    int t = threadIdx.x;
    int v = (t < nb) ? g_bsum[t] : 0;
    sh[t] = v;
    __syncthreads();
    #pragma unroll
    for (int o = 1; o < 512; o <<= 1) {
        int u = (t >= o) ? sh[t - o] : 0;
        __syncthreads();
        sh[t] += u;
        __syncthreads();
    }
    if (t < nb) g_bsum[t] = sh[t] - v;
}

__global__ void scan_final(int n, long long E) {
    int t = threadIdx.x, lane = t & 31, wid = t >> 5;
    int i = blockIdx.x * 256 + t;
    int v = (i < n) ? g_deg[i] : 0;
    int incl = v;
    #pragma unroll
    for (int o = 1; o < 32; o <<= 1) {
        int u = __shfl_up_sync(0xffffffffu, incl, o);
        if (lane >= o) incl += u;
    }
    __shared__ int ws[8], wso[8];
    if (lane == 31) ws[wid] = incl;
    __syncthreads();
    if (t == 0) {
        int s = 0;
        #pragma unroll
        for (int k = 0; k < 8; k++) { wso[k] = s; s += ws[k]; }
    }
    __syncthreads();
    int excl = incl - v + wso[wid] + g_bsum[blockIdx.x];
    if (i < n) { g_rowptr[i] = excl; g_cursor[i] = excl; }
    if (i == n - 1) g_rowptr[n] = (int)E;
}

__global__ void fill_kernel(const void* __restrict__ ei, long long E) {
    long long i = (long long)blockIdx.x * blockDim.x + threadIdx.x;
    if (i >= E) return;
    int s = ld_idx(ei, i);
    int d = ld_idx(ei, E + i);
    int pos = atomicAdd(&g_cursor[d], 1);
    g_csrc[pos] = s;
}

// ======================= W split+transpose into swizzled images =======================
__global__ void wprep(const float* __restrict__ W1, const float* __restrict__ W2,
                      uint32_t* __restrict__ img) {
    int i = blockIdx.x * 256 + threadIdx.x;      // 2 layers * 128 n * 64 k2
    if (i >= 16384) return;
    int l = i >> 13, rem = i & 8191;
    int nrow = rem >> 6, k2 = rem & 63;
    const float* W = l ? W2 : W1;
    float x0 = W[(2 * k2) * 128 + nrow];
    float x1 = W[(2 * k2 + 1) * 128 + nrow];
    __nv_bfloat16 h0 = __float2bfloat16(x0);
    __nv_bfloat16 h1 = __float2bfloat16(x1);
    __nv_bfloat16 l0 = __float2bfloat16(x0 - __bfloat162float(h0));
    __nv_bfloat16 l1 = __float2bfloat16(x1 - __bfloat162float(h1));
    uint32_t hw = ((uint32_t)__bfloat16_as_ushort(h1) << 16) | __bfloat16_as_ushort(h0);
    uint32_t lw = ((uint32_t)__bfloat16_as_ushort(l1) << 16) | __bfloat16_as_ushort(l0);
    uint32_t widx = blk_off(nrow, 2 * k2) >> 2;
    img[l * 16384 + widx] = hw;
    img[l * 16384 + 8192 + widx] = lw;
}

// ======================= HMMA GEMM: outA = X @ W (unscaled) =======================
#define SM_AHI 0
#define SM_ALO 32768
#define SM_BHI 65536
#define SM_BLO 98304
#define GEMM_SMEM 131072

__global__ void __launch_bounds__(256, 1)
gemm_tc(const float* __restrict__ X, const uint32_t* __restrict__ Wimg,
        float* __restrict__ outA, int n) {
    extern __shared__ char sm[];
    uint32_t smem_base = smem_u32(sm);
    int t = threadIdx.x;
    int w = t >> 5, lane = t & 31;
    int row0 = blockIdx.x * 128;

    // ---- load X tile, split into bf16 hi/lo, write blocked+swizzled SMEM ----
    {
        int lrow = t >> 1;
        int kh = t & 1;
        int row = row0 + lrow;
        const float4* X4 = (const float4*)X;
        #pragma unroll 4
        for (int i = 0; i < 16; i++) {
            float4 v = (row < n) ? X4[(size_t)row * 32 + kh * 16 + i]
                                 : make_float4(0.f, 0.f, 0.f, 0.f);
            int k = kh * 64 + i * 4;
            __nv_bfloat16 hx = __float2bfloat16(v.x), hy = __float2bfloat16(v.y);
            __nv_bfloat16 hz = __float2bfloat16(v.z), hw_ = __float2bfloat16(v.w);
            __nv_bfloat16 lx = __float2bfloat16(v.x - __bfloat162float(hx));
            __nv_bfloat16 ly = __float2bfloat16(v.y - __bfloat162float(hy));
            __nv_bfloat16 lz = __float2bfloat16(v.z - __bfloat162float(hz));
            __nv_bfloat16 lw = __float2bfloat16(v.w - __bfloat162float(hw_));
            uint32_t hi0 = ((uint32_t)__bfloat16_as_ushort(hy) << 16) | __bfloat16_as_ushort(hx);
            uint32_t hi1 = ((uint32_t)__bfloat16_as_ushort(hw_) << 16) | __bfloat16_as_ushort(hz);
            uint32_t lo0 = ((uint32_t)__bfloat16_as_ushort(ly) << 16) | __bfloat16_as_ushort(lx);
            uint32_t lo1 = ((uint32_t)__bfloat16_as_ushort(lw) << 16) | __bfloat16_as_ushort(lz);
            uint32_t o0 = blk_off(lrow, k), o1 = blk_off(lrow, k + 2);
            *(uint32_t*)(sm + SM_AHI + o0) = hi0;
            *(uint32_t*)(sm + SM_AHI + o1) = hi1;
            *(uint32_t*)(sm + SM_ALO + o0) = lo0;
            *(uint32_t*)(sm + SM_ALO + o1) = lo1;
        }
    }
    // ---- copy pre-swizzled W images ----
    {
        const uint4* sh = (const uint4*)Wimg;
        const uint4* sl = (const uint4*)(Wimg + 8192);
        uint4* dh = (uint4*)(sm + SM_BHI);
        uint4* dl = (uint4*)(sm + SM_BLO);
        #pragma unroll
        for (int i = 0; i < 8; i++) {
            dh[t + 256 * i] = sh[t + 256 * i];
            dl[t + 256 * i] = sl[t + 256 * i];
        }
    }
    __syncthreads();

    int mwarp = (w & 3) * 32;
    int nwarp = (w >> 2) * 64;

    float acc[2][8][4];
    #pragma unroll
    for (int mi = 0; mi < 2; mi++)
        #pragma unroll
        for (int nj = 0; nj < 8; nj++)
            #pragma unroll
            for (int q = 0; q < 4; q++) acc[mi][nj][q] = 0.f;

    int a_row = mwarp + (lane & 15);
    int a_kof = (lane >> 4) << 3;
    int b_row = nwarp + (lane & 7) + ((lane >> 4) << 3);
    int b_kof = (lane & 8);

    const uint32_t Aoff[3] = { SM_AHI, SM_AHI, SM_ALO };
    const uint32_t Boff[3] = { SM_BHI, SM_BLO, SM_BHI };

    #pragma unroll
    for (int p = 0; p < 3; p++) {
        uint32_t Abase = smem_base + Aoff[p];
        uint32_t Bbase = smem_base + Boff[p];
        #pragma unroll
        for (int ks = 0; ks < 8; ks++) {
            int k0 = ks * 16;
            uint32_t a[2][4];
            ldsm4(a[0], Abase + blk_off(a_row,      k0 + a_kof));
            ldsm4(a[1], Abase + blk_off(a_row + 16, k0 + a_kof));
            uint32_t b[4][4];
            #pragma unroll
            for (int g = 0; g < 4; g++)
                ldsm4(b[g], Bbase + blk_off(b_row + g * 16, k0 + b_kof));
            #pragma unroll
            for (int mi = 0; mi < 2; mi++)
                #pragma unroll
                for (int g = 0; g < 4; g++) {
                    mma_bf16(acc[mi][2 * g],     a[mi], b[g][0], b[g][1]);
                    mma_bf16(acc[mi][2 * g + 1], a[mi], b[g][2], b[g][3]);
                }
        }
    }

    // ---- epilogue: store raw h (no dinv scale — graph-independent) ----
    {
        int g = lane >> 2, i2 = lane & 3;
        #pragma unroll
        for (int mi = 0; mi < 2; mi++) {
            int r0 = row0 + mwarp + mi * 16 + g;
            int r1 = r0 + 8;
            #pragma unroll
            for (int nj = 0; nj < 8; nj++) {
                int c = nwarp + nj * 8 + 2 * i2;
                if (r0 < n)
                    *(float2*)(outA + (size_t)r0 * 128 + c) =
                        make_float2(acc[mi][nj][0], acc[mi][nj][1]);
                if (r1 < n)
                    *(float2*)(outA + (size_t)r1 * 128 + c) =
                        make_float2(acc[mi][nj][2], acc[mi][nj][3]);
            }
        }
    }
}

// ======================= CSR gather (applies dinv[src] per message) =======================
__global__ void gather_kernel(const float* __restrict__ A, float* __restrict__ B,
                              const float* __restrict__ bias, int n, int relu) {
    int node = blockIdx.x * (blockDim.x >> 5) + (threadIdx.x >> 5);
    int lane = threadIdx.x & 31;
    if (node >= n) return;
    int beg = g_rowptr[node], end = g_rowptr[node + 1];
    const float4* A4 = (const float4*)A;

    float dself = g_dinv[node];
    float4 acc = A4[(size_t)node * 32 + lane];
    acc.x *= dself; acc.y *= dself; acc.z *= dself; acc.w *= dself;  // self-loop msg

    for (int j0 = beg; j0 < end; j0 += 32) {
        int m = min(32, end - j0);
        int idx = 0; float dv = 0.f;
        if (lane < m) {
            idx = g_csrc[j0 + lane];
            dv = g_dinv[idx];
        }
        int k = 0;
        for (; k + 4 <= m; k += 4) {
            int s0 = __shfl_sync(0xffffffffu, idx, k);
            int s1 = __shfl_sync(0xffffffffu, idx, k + 1);
            int s2 = __shfl_sync(0xffffffffu, idx, k + 2);
            int s3 = __shfl_sync(0xffffffffu, idx, k + 3);
            float d0 = __shfl_sync(0xffffffffu, dv, k);
            float d1 = __shfl_sync(0xffffffffu, dv, k + 1);
            float d2 = __shfl_sync(0xffffffffu, dv, k + 2);
            float d3 = __shfl_sync(0xffffffffu, dv, k + 3);
            float4 v0 = A4[(size_t)s0 * 32 + lane];
            float4 v1 = A4[(size_t)s1 * 32 + lane];
            float4 v2 = A4[(size_t)s2 * 32 + lane];
            float4 v3 = A4[(size_t)s3 * 32 + lane];
            acc.x = fmaf(v0.x, d0, fmaf(v1.x, d1, fmaf(v2.x, d2, fmaf(v3.x, d3, acc.x))));
            acc.y = fmaf(v0.y, d0, fmaf(v1.y, d1, fmaf(v2.y, d2, fmaf(v3.y, d3, acc.y))));
            acc.z = fmaf(v0.z, d0, fmaf(v1.z, d1, fmaf(v2.z, d2, fmaf(v3.z, d3, acc.z))));
            acc.w = fmaf(v0.w, d0, fmaf(v1.w, d1, fmaf(v2.w, d2, fmaf(v3.w, d3, acc.w))));
        }
        for (; k < m; k++) {
            int s = __shfl_sync(0xffffffffu, idx, k);
            float d = __shfl_sync(0xffffffffu, dv, k);
            float4 v = A4[(size_t)s * 32 + lane];
            acc.x = fmaf(v.x, d, acc.x);
            acc.y = fmaf(v.y, d, acc.y);
            acc.z = fmaf(v.z, d, acc.z);
            acc.w = fmaf(v.w, d, acc.w);
        }
    }

    float4 bb = ((const float4*)bias)[lane];
    float4 o;
    o.x = fmaf(acc.x, dself, bb.x);
    o.y = fmaf(acc.y, dself, bb.y);
    o.z = fmaf(acc.z, dself, bb.z);
    o.w = fmaf(acc.w, dself, bb.w);
    if (relu) {
        o.x = fmaxf(o.x, 0.f); o.y = fmaxf(o.y, 0.f);
        o.z = fmaxf(o.z, 0.f); o.w = fmaxf(o.w, 0.f);
    }
    ((float4*)B)[(size_t)node * 32 + lane] = o;
}

// ======================= decode =======================
__global__ void decode_kernel(const void* __restrict__ eli, long long M,
                              const float* __restrict__ Z, float* __restrict__ out) {
    long long w = (long long)blockIdx.x * (blockDim.x >> 5) + (threadIdx.x >> 5);
    int lane = threadIdx.x & 31;
    if (w >= M) return;
    int s = 0, d = 0;
    if (lane == 0) {
        s = ld_idx(eli, w);
        d = ld_idx(eli, M + w);
    }
    s = __shfl_sync(0xffffffffu, s, 0);
    d = __shfl_sync(0xffffffffu, d, 0);
    float4 a = ((const float4*)Z)[(size_t)s * 32 + lane];
    float4 b = ((const float4*)Z)[(size_t)d * 32 + lane];
    float sum = a.x * b.x + a.y * b.y + a.z * b.z + a.w * b.w;
    #pragma unroll
    for (int o = 16; o; o >>= 1) sum += __shfl_xor_sync(0xffffffffu, sum, o);
    if (lane == 0) out[w] = sum;
}

// ======================= launch =======================
extern "C" void kernel_launch(void* const* d_in, const int* in_sizes, int n_in,
                              void* d_out, int out_size) {
    const float* x   = (const float*)d_in[0];
    const void*  ei  = d_in[1];
    const void*  eli = d_in[2];
    const float* W1  = (const float*)d_in[3];
    const float* b1  = (const float*)d_in[4];
    const float* W2  = (const float*)d_in[5];
    const float* b2  = (const float*)d_in[6];
    float* out = (float*)d_out;

    int n = in_sizes[0] / DIM;
    long long E = in_sizes[1] / 2;
    long long M = in_sizes[2] / 2;

    float *pA = nullptr, *pB = nullptr;
    uint32_t* pW = nullptr;
    int* pDeg = nullptr;
    cudaGetSymbolAddress((void**)&pA, g_bufA);
    cudaGetSymbolAddress((void**)&pB, g_bufB);
    cudaGetSymbolAddress((void**)&pW, g_Wimg);
    cudaGetSymbolAddress((void**)&pDeg, g_deg);
    cudaFuncSetAttribute(gemm_tc, cudaFuncAttributeMaxDynamicSharedMemorySize, GEMM_SMEM);

    // One-time side-stream + events (handles only; no device allocations here)
    static cudaStream_t sB = nullptr;
    static cudaEvent_t evFork = nullptr, evJoin = nullptr;
    if (sB == nullptr) {
        cudaStreamCreateWithFlags(&sB, cudaStreamNonBlocking);
        cudaEventCreateWithFlags(&evFork, cudaEventDisableTiming);
        cudaEventCreateWithFlags(&evJoin, cudaEventDisableTiming);
    }

    int nb256 = (n + 255) / 256;
    int eb    = (int)((E + 255) / 256);
    int mbw   = (int)((M + 7) / 8);
    int gbw   = (n + 7) / 8;
    int gemmb = (n + 127) / 128;

    // ---- fork: preprocessing on sB, GEMM path on default stream ----
    cudaEventRecord(evFork, 0);
    cudaStreamWaitEvent(sB, evFork, 0);

    // preproc chain (stream sB)
    detect_kernel<<<1, 32, 0, sB>>>((const unsigned int*)ei);
    cudaMemsetAsync(pDeg, 0, (size_t)n * sizeof(int), sB);
    deg_count<<<eb, 256, 0, sB>>>(ei, E);
    scan_partial<<<nb256, 256, 0, sB>>>(n);
    scan_top<<<1, 512, 0, sB>>>(nb256);
    scan_final<<<nb256, 256, 0, sB>>>(n, E);
    fill_kernel<<<eb, 256, 0, sB>>>(ei, E);
    cudaEventRecord(evJoin, sB);

    // GEMM path (default stream), independent of the graph
    wprep<<<64, 256>>>(W1, W2, pW);
    gemm_tc<<<gemmb, 256, GEMM_SMEM>>>(x, pW, pA, n);

    // ---- join ----
    cudaStreamWaitEvent(0, evJoin, 0);

    // Layer 1 aggregate
    gather_kernel<<<gbw, 256>>>(pA, pB, b1, n, 1);

    // Layer 2
    gemm_tc<<<gemmb, 256, GEMM_SMEM>>>(pB, pW + 16384, pA, n);
    gather_kernel<<<gbw, 256>>>(pA, pB, b2, n, 0);

    // Decode
    decode_kernel<<<mbw, 256>>>(eli, M, pB, out);
}

// round 7
// speedup vs baseline: 2.1575x; 1.0101x over previous
#include <cuda_runtime.h>
#include <cuda_bf16.h>
#include <cuda_fp16.h>
#include <math.h>
#include <stdint.h>

#define DIM 128
#define NMAX 100000
#define EMAX 2000000

// Scratch (allocation-free rule: __device__ globals)
__device__ __half   g_bufA[(size_t)NMAX * DIM];   // h messages (fp16, unscaled)
__device__ float    g_bufB[(size_t)NMAX * DIM];   // activations (fp32)
__device__ int      g_deg[NMAX];
__device__ float    g_dinv[NMAX];
__device__ int      g_rowptr[NMAX + 1];
__device__ int      g_cursor[NMAX];
__device__ int      g_csrc[EMAX];
__device__ int      g_bsum[512];
__device__ int      g_is64;
__device__ uint32_t g_Wimg[2][2][8192];           // [layer][hi/lo][swizzled bf16x2 image]

// ======================= helpers =======================
__device__ __forceinline__ uint32_t smem_u32(const void* p) {
    uint32_t a;
    asm("{ .reg .u64 t; cvta.to.shared.u64 t, %1; cvt.u32.u64 %0, t; }" : "=r"(a) : "l"(p));
    return a;
}

// Blocked SW128 atom layout for a [rows=128, K=128] bf16 tile.
__host__ __device__ __forceinline__ uint32_t blk_off(int row, int col /*bf16 idx*/) {
    uint32_t off = (uint32_t)((row >> 3) + (col >> 6) * 16) * 1024u
                 + (uint32_t)(row & 7) * 128u + (uint32_t)(col & 63) * 2u;
    return off ^ ((off >> 3) & 0x70u);
}

__device__ __forceinline__ void ldsm4(uint32_t* r, uint32_t addr) {
    asm volatile("ldmatrix.sync.aligned.m8n8.x4.shared.b16 {%0,%1,%2,%3}, [%4];"
                 : "=r"(r[0]), "=r"(r[1]), "=r"(r[2]), "=r"(r[3]) : "r"(addr));
}

__device__ __forceinline__ void mma_bf16(float* d, const uint32_t* a,
                                         uint32_t b0, uint32_t b1) {
    asm volatile(
        "mma.sync.aligned.m16n8k16.row.col.f32.bf16.bf16.f32 "
        "{%0,%1,%2,%3}, {%4,%5,%6,%7}, {%8,%9}, {%0,%1,%2,%3};"
        : "+f"(d[0]), "+f"(d[1]), "+f"(d[2]), "+f"(d[3])
        : "r"(a[0]), "r"(a[1]), "r"(a[2]), "r"(a[3]), "r"(b0), "r"(b1));
}

// ======================= index dtype detection =======================
__global__ void detect_kernel(const unsigned int* __restrict__ p) {
    if (threadIdx.x == 0 && blockIdx.x == 0) {
        int is64 = 1;
        #pragma unroll
        for (int i = 0; i < 64; i++)
            if (p[2 * i + 1] != 0u) is64 = 0;
        g_is64 = is64;
    }
}

__device__ __forceinline__ int ld_idx(const void* p, long long i) {
    if (g_is64) return (int)((const long long*)p)[i];
    return ((const int*)p)[i];
}

// ======================= degree =======================
__global__ void deg_count(const void* __restrict__ ei, long long E) {
    long long i = (long long)blockIdx.x * blockDim.x + threadIdx.x;
    if (i < E) atomicAdd(&g_deg[ld_idx(ei, E + i)], 1);
}

// ======================= prefix scan -> CSR (+ dinv fused) =======================
__global__ void scan_partial(int n) {
    int i = blockIdx.x * 256 + threadIdx.x;
    int v = (i < n) ? g_deg[i] : 0;
    if (i < n) g_dinv[i] = rsqrtf((float)(v + 1));  // fused dinv (+1 self loop)
    int s = v;
    #pragma unroll
    for (int o = 16; o; o >>= 1) s += __shfl_down_sync(0xffffffffu, s, o);
    __shared__ int ws[8];
    if ((threadIdx.x & 31) == 0) ws[threadIdx.x >> 5] = s;
    __syncthreads();
    if (threadIdx.x == 0) {
        int t = 0;
        #pragma unroll
        for (int k = 0; k < 8; k++) t += ws[k];
        g_bsum[blockIdx.x] = t;
    }
}

__global__ void scan_top(int nb) {
    __shared__ int sh[512];
    int t = threadIdx.x;
    int v = (t < nb) ? g_bsum[t] : 0;
    sh[t] = v;
    __syncthreads();
    #pragma unroll
    for (int o = 1; o < 512; o <<= 1) {
        int u = (t >= o) ? sh[t - o] : 0;
        __syncthreads();
        sh[t] += u;
        __syncthreads();
    }
    if (t < nb) g_bsum[t] = sh[t] - v;
}

__global__ void scan_final(int n, long long E) {
    int t = threadIdx.x, lane = t & 31, wid = t >> 5;
    int i = blockIdx.x * 256 + t;
    int v = (i < n) ? g_deg[i] : 0;
    int incl = v;
    #pragma unroll
    for (int o = 1; o < 32; o <<= 1) {
        int u = __shfl_up_sync(0xffffffffu, incl, o);
        if (lane >= o) incl += u;
    }
    __shared__ int ws[8], wso[8];
    if (lane == 31) ws[wid] = incl;
    __syncthreads();
    if (t == 0) {
        int s = 0;
        #pragma unroll
        for (int k = 0; k < 8; k++) { wso[k] = s; s += ws[k]; }
    }
    __syncthreads();
    int excl = incl - v + wso[wid] + g_bsum[blockIdx.x];
    if (i < n) { g_rowptr[i] = excl; g_cursor[i] = excl; }
    if (i == n - 1) g_rowptr[n] = (int)E;
}

__global__ void fill_kernel(const void* __restrict__ ei, long long E) {
    long long i = (long long)blockIdx.x * blockDim.x + threadIdx.x;
    if (i >= E) return;
    int s = ld_idx(ei, i);
    int d = ld_idx(ei, E + i);
    int pos = atomicAdd(&g_cursor[d], 1);
    g_csrc[pos] = s;
}

// ======================= W split+transpose into swizzled images =======================
__global__ void wprep(const float* __restrict__ W1, const float* __restrict__ W2,
                      uint32_t* __restrict__ img) {
    int i = blockIdx.x * 256 + threadIdx.x;      // 2 layers * 128 n * 64 k2
    if (i >= 16384) return;
    int l = i >> 13, rem = i & 8191;
    int nrow = rem >> 6, k2 = rem & 63;
    const float* W = l ? W2 : W1;
    float x0 = W[(2 * k2) * 128 + nrow];
    float x1 = W[(2 * k2 + 1) * 128 + nrow];
    __nv_bfloat16 h0 = __float2bfloat16(x0);
    __nv_bfloat16 h1 = __float2bfloat16(x1);
    __nv_bfloat16 l0 = __float2bfloat16(x0 - __bfloat162float(h0));
    __nv_bfloat16 l1 = __float2bfloat16(x1 - __bfloat162float(h1));
    uint32_t hw = ((uint32_t)__bfloat16_as_ushort(h1) << 16) | __bfloat16_as_ushort(h0);
    uint32_t lw = ((uint32_t)__bfloat16_as_ushort(l1) << 16) | __bfloat16_as_ushort(l0);
    uint32_t widx = blk_off(nrow, 2 * k2) >> 2;
    img[l * 16384 + widx] = hw;
    img[l * 16384 + 8192 + widx] = lw;
}

// ======================= HMMA GEMM: outA = fp16(X @ W) =======================
#define SM_AHI 0
#define SM_ALO 32768
#define SM_BHI 65536
#define SM_BLO 98304
#define GEMM_SMEM 131072

__global__ void __launch_bounds__(256, 1)
gemm_tc(const float* __restrict__ X, const uint32_t* __restrict__ Wimg,
        __half* __restrict__ outA, int n) {
    extern __shared__ char sm[];
    uint32_t smem_base = smem_u32(sm);
    int t = threadIdx.x;
    int w = t >> 5, lane = t & 31;
    int row0 = blockIdx.x * 128;

    // ---- load X tile, split into bf16 hi/lo, write blocked+swizzled SMEM ----
    {
        int lrow = t >> 1;
        int kh = t & 1;
        int row = row0 + lrow;
        const float4* X4 = (const float4*)X;
        #pragma unroll 4
        for (int i = 0; i < 16; i++) {
            float4 v = (row < n) ? X4[(size_t)row * 32 + kh * 16 + i]
                                 : make_float4(0.f, 0.f, 0.f, 0.f);
            int k = kh * 64 + i * 4;
            __nv_bfloat16 hx = __float2bfloat16(v.x), hy = __float2bfloat16(v.y);
            __nv_bfloat16 hz = __float2bfloat16(v.z), hw_ = __float2bfloat16(v.w);
            __nv_bfloat16 lx = __float2bfloat16(v.x - __bfloat162float(hx));
            __nv_bfloat16 ly = __float2bfloat16(v.y - __bfloat162float(hy));
            __nv_bfloat16 lz = __float2bfloat16(v.z - __bfloat162float(hz));
            __nv_bfloat16 lw = __float2bfloat16(v.w - __bfloat162float(hw_));
            uint32_t hi0 = ((uint32_t)__bfloat16_as_ushort(hy) << 16) | __bfloat16_as_ushort(hx);
            uint32_t hi1 = ((uint32_t)__bfloat16_as_ushort(hw_) << 16) | __bfloat16_as_ushort(hz);
            uint32_t lo0 = ((uint32_t)__bfloat16_as_ushort(ly) << 16) | __bfloat16_as_ushort(lx);
            uint32_t lo1 = ((uint32_t)__bfloat16_as_ushort(lw) << 16) | __bfloat16_as_ushort(lz);
            uint32_t o0 = blk_off(lrow, k), o1 = blk_off(lrow, k + 2);
            *(uint32_t*)(sm + SM_AHI + o0) = hi0;
            *(uint32_t*)(sm + SM_AHI + o1) = hi1;
            *(uint32_t*)(sm + SM_ALO + o0) = lo0;
            *(uint32_t*)(sm + SM_ALO + o1) = lo1;
        }
    }
    // ---- copy pre-swizzled W images ----
    {
        const uint4* sh = (const uint4*)Wimg;
        const uint4* sl = (const uint4*)(Wimg + 8192);
        uint4* dh = (uint4*)(sm + SM_BHI);
        uint4* dl = (uint4*)(sm + SM_BLO);
        #pragma unroll
        for (int i = 0; i < 8; i++) {
            dh[t + 256 * i] = sh[t + 256 * i];
            dl[t + 256 * i] = sl[t + 256 * i];
        }
    }
    __syncthreads();

    int mwarp = (w & 3) * 32;
    int nwarp = (w >> 2) * 64;

    float acc[2][8][4];
    #pragma unroll
    for (int mi = 0; mi < 2; mi++)
        #pragma unroll
        for (int nj = 0; nj < 8; nj++)
            #pragma unroll
            for (int q = 0; q < 4; q++) acc[mi][nj][q] = 0.f;

    int a_row = mwarp + (lane & 15);
    int a_kof = (lane >> 4) << 3;
    int b_row = nwarp + (lane & 7) + ((lane >> 4) << 3);
    int b_kof = (lane & 8);

    const uint32_t Aoff[3] = { SM_AHI, SM_AHI, SM_ALO };
    const uint32_t Boff[3] = { SM_BHI, SM_BLO, SM_BHI };

    #pragma unroll
    for (int p = 0; p < 3; p++) {
        uint32_t Abase = smem_base + Aoff[p];
        uint32_t Bbase = smem_base + Boff[p];
        #pragma unroll
        for (int ks = 0; ks < 8; ks++) {
            int k0 = ks * 16;
            uint32_t a[2][4];
            ldsm4(a[0], Abase + blk_off(a_row,      k0 + a_kof));
            ldsm4(a[1], Abase + blk_off(a_row + 16, k0 + a_kof));
            uint32_t b[4][4];
            #pragma unroll
            for (int g = 0; g < 4; g++)
                ldsm4(b[g], Bbase + blk_off(b_row + g * 16, k0 + b_kof));
            #pragma unroll
            for (int mi = 0; mi < 2; mi++)
                #pragma unroll
                for (int g = 0; g < 4; g++) {
                    mma_bf16(acc[mi][2 * g],     a[mi], b[g][0], b[g][1]);
                    mma_bf16(acc[mi][2 * g + 1], a[mi], b[g][2], b[g][3]);
                }
        }
    }

    // ---- epilogue: store raw h as fp16 ----
    {
        int g = lane >> 2, i2 = lane & 3;
        #pragma unroll
        for (int mi = 0; mi < 2; mi++) {
            int r0 = row0 + mwarp + mi * 16 + g;
            int r1 = r0 + 8;
            #pragma unroll
            for (int nj = 0; nj < 8; nj++) {
                int c = nwarp + nj * 8 + 2 * i2;
                if (r0 < n)
                    *(__half2*)(outA + (size_t)r0 * 128 + c) =
                        __floats2half2_rn(acc[mi][nj][0], acc[mi][nj][1]);
                if (r1 < n)
                    *(__half2*)(outA + (size_t)r1 * 128 + c) =
                        __floats2half2_rn(acc[mi][nj][2], acc[mi][nj][3]);
            }
        }
    }
}

// ======================= CSR gather (fp16 messages, fp32 accum) =======================
__global__ void gather_kernel(const __half* __restrict__ A, float* __restrict__ B,
                              const float* __restrict__ bias, int n, int relu) {
    int node = blockIdx.x * (blockDim.x >> 5) + (threadIdx.x >> 5);
    int lane = threadIdx.x & 31;
    if (node >= n) return;
    int beg = g_rowptr[node], end = g_rowptr[node + 1];
    const uint2* A2 = (const uint2*)A;   // 32 uint2 per row

    float dself = g_dinv[node];
    float4 acc;
    {
        uint2 u = A2[(size_t)node * 32 + lane];
        float2 p0 = __half22float2(*(const __half2*)&u.x);
        float2 p1 = __half22float2(*(const __half2*)&u.y);
        acc.x = p0.x * dself; acc.y = p0.y * dself;
        acc.z = p1.x * dself; acc.w = p1.y * dself;
    }

    for (int j0 = beg; j0 < end; j0 += 32) {
        int m = min(32, end - j0);
        int idx = 0; float dv = 0.f;
        if (lane < m) {
            idx = g_csrc[j0 + lane];
            dv = g_dinv[idx];
        }
        int k = 0;
        for (; k + 4 <= m; k += 4) {
            int s0 = __shfl_sync(0xffffffffu, idx, k);
            int s1 = __shfl_sync(0xffffffffu, idx, k + 1);
            int s2 = __shfl_sync(0xffffffffu, idx, k + 2);
            int s3 = __shfl_sync(0xffffffffu, idx, k + 3);
            float d0 = __shfl_sync(0xffffffffu, dv, k);
            float d1 = __shfl_sync(0xffffffffu, dv, k + 1);
            float d2 = __shfl_sync(0xffffffffu, dv, k + 2);
            float d3 = __shfl_sync(0xffffffffu, dv, k + 3);
            uint2 u0 = A2[(size_t)s0 * 32 + lane];
            uint2 u1 = A2[(size_t)s1 * 32 + lane];
            uint2 u2 = A2[(size_t)s2 * 32 + lane];
            uint2 u3 = A2[(size_t)s3 * 32 + lane];
            float2 a0 = __half22float2(*(const __half2*)&u0.x);
            float2 b0v = __half22float2(*(const __half2*)&u0.y);
            float2 a1 = __half22float2(*(const __half2*)&u1.x);
            float2 b1v = __half22float2(*(const __half2*)&u1.y);
            float2 a2 = __half22float2(*(const __half2*)&u2.x);
            float2 b2v = __half22float2(*(const __half2*)&u2.y);
            float2 a3 = __half22float2(*(const __half2*)&u3.x);
            float2 b3v = __half22float2(*(const __half2*)&u3.y);
            acc.x = fmaf(a0.x, d0, fmaf(a1.x, d1, fmaf(a2.x, d2, fmaf(a3.x, d3, acc.x))));
            acc.y = fmaf(a0.y, d0, fmaf(a1.y, d1, fmaf(a2.y, d2, fmaf(a3.y, d3, acc.y))));
            acc.z = fmaf(b0v.x, d0, fmaf(b1v.x, d1, fmaf(b2v.x, d2, fmaf(b3v.x, d3, acc.z))));
            acc.w = fmaf(b0v.y, d0, fmaf(b1v.y, d1, fmaf(b2v.y, d2, fmaf(b3v.y, d3, acc.w))));
        }
        for (; k < m; k++) {
            int s = __shfl_sync(0xffffffffu, idx, k);
            float d = __shfl_sync(0xffffffffu, dv, k);
            uint2 u = A2[(size_t)s * 32 + lane];
            float2 p0 = __half22float2(*(const __half2*)&u.x);
            float2 p1 = __half22float2(*(const __half2*)&u.y);
            acc.x = fmaf(p0.x, d, acc.x);
            acc.y = fmaf(p0.y, d, acc.y);
            acc.z = fmaf(p1.x, d, acc.z);
            acc.w = fmaf(p1.y, d, acc.w);
        }
    }

    float4 bb = ((const float4*)bias)[lane];
    float4 o;
    o.x = fmaf(acc.x, dself, bb.x);
    o.y = fmaf(acc.y, dself, bb.y);
    o.z = fmaf(acc.z, dself, bb.z);
    o.w = fmaf(acc.w, dself, bb.w);
    if (relu) {
        o.x = fmaxf(o.x, 0.f); o.y = fmaxf(o.y, 0.f);
        o.z = fmaxf(o.z, 0.f); o.w = fmaxf(o.w, 0.f);
    }
    ((float4*)B)[(size_t)node * 32 + lane] = o;
}

// ======================= decode =======================
__global__ void decode_kernel(const void* __restrict__ eli, long long M,
                              const float* __restrict__ Z, float* __restrict__ out) {
    long long w = (long long)blockIdx.x * (blockDim.x >> 5) + (threadIdx.x >> 5);
    int lane = threadIdx.x & 31;
    if (w >= M) return;
    int s = 0, d = 0;
    if (lane == 0) {
        s = ld_idx(eli, w);
        d = ld_idx(eli, M + w);
    }
    s = __shfl_sync(0xffffffffu, s, 0);
    d = __shfl_sync(0xffffffffu, d, 0);
    float4 a = ((const float4*)Z)[(size_t)s * 32 + lane];
    float4 b = ((const float4*)Z)[(size_t)d * 32 + lane];
    float sum = a.x * b.x + a.y * b.y + a.z * b.z + a.w * b.w;
    #pragma unroll
    for (int o = 16; o; o >>= 1) sum += __shfl_xor_sync(0xffffffffu, sum, o);
    if (lane == 0) out[w] = sum;
}

// ======================= launch =======================
extern "C" void kernel_launch(void* const* d_in, const int* in_sizes, int n_in,
                              void* d_out, int out_size) {
    const float* x   = (const float*)d_in[0];
    const void*  ei  = d_in[1];
    const void*  eli = d_in[2];
    const float* W1  = (const float*)d_in[3];
    const float* b1  = (const float*)d_in[4];
    const float* W2  = (const float*)d_in[5];
    const float* b2  = (const float*)d_in[6];
    float* out = (float*)d_out;

    int n = in_sizes[0] / DIM;
    long long E = in_sizes[1] / 2;
    long long M = in_sizes[2] / 2;

    __half* pA = nullptr;
    float* pB = nullptr;
    uint32_t* pW = nullptr;
    int* pDeg = nullptr;
    cudaGetSymbolAddress((void**)&pA, g_bufA);
    cudaGetSymbolAddress((void**)&pB, g_bufB);
    cudaGetSymbolAddress((void**)&pW, g_Wimg);
    cudaGetSymbolAddress((void**)&pDeg, g_deg);
    cudaFuncSetAttribute(gemm_tc, cudaFuncAttributeMaxDynamicSharedMemorySize, GEMM_SMEM);

    // Optional side-stream: fall back to single-stream if creation fails.
    static cudaStream_t sB = nullptr;
    static cudaEvent_t evFork = nullptr, evJoin = nullptr;
    static int streamTried = 0;
    if (!streamTried) {
        streamTried = 1;
        if (cudaStreamCreateWithFlags(&sB, cudaStreamNonBlocking) != cudaSuccess) sB = nullptr;
        if (sB) {
            if (cudaEventCreateWithFlags(&evFork, cudaEventDisableTiming) != cudaSuccess ||
                cudaEventCreateWithFlags(&evJoin, cudaEventDisableTiming) != cudaSuccess) {
                sB = nullptr;
            }
        }
        cudaGetLastError();  // clear any sticky-free error state
    }
    cudaStream_t sP = sB ? sB : (cudaStream_t)0;  // preproc stream

    int nb256 = (n + 255) / 256;
    int eb    = (int)((E + 255) / 256);
    int mbw   = (int)((M + 7) / 8);
    int gbw   = (n + 7) / 8;
    int gemmb = (n + 127) / 128;

    // ---- fork: preprocessing on sP, GEMM path on default stream ----
    if (sB) {
        cudaEventRecord(evFork, 0);
        cudaStreamWaitEvent(sB, evFork, 0);
    }

    detect_kernel<<<1, 32, 0, sP>>>((const unsigned int*)ei);
    cudaMemsetAsync(pDeg, 0, (size_t)n * sizeof(int), sP);
    deg_count<<<eb, 256, 0, sP>>>(ei, E);
    scan_partial<<<nb256, 256, 0, sP>>>(n);
    scan_top<<<1, 512, 0, sP>>>(nb256);
    scan_final<<<nb256, 256, 0, sP>>>(n, E);
    fill_kernel<<<eb, 256, 0, sP>>>(ei, E);
    if (sB) cudaEventRecord(evJoin, sB);

    // GEMM path (default stream), independent of the graph structure
    wprep<<<64, 256>>>(W1, W2, pW);
    gemm_tc<<<gemmb, 256, GEMM_SMEM>>>(x, pW, pA, n);

    // ---- join ----
    if (sB) cudaStreamWaitEvent(0, evJoin, 0);

    // Layer 1 aggregate
    gather_kernel<<<gbw, 256>>>(pA, pB, b1, n, 1);

    // Layer 2
    gemm_tc<<<gemmb, 256, GEMM_SMEM>>>(pB, pW + 16384, pA, n);
    gather_kernel<<<gbw, 256>>>(pA, pB, b2, n, 0);

    // Decode
    decode_kernel<<<mbw, 256>>>(eli, M, pB, out);
}

// round 8
// speedup vs baseline: 2.5472x; 1.1806x over previous
#include <cuda_runtime.h>
#include <cuda_bf16.h>
#include <cuda_fp16.h>
#include <math.h>
#include <stdint.h>

#define DIM 128
#define NMAX 100000
#define EMAX 2000000

// Scratch (allocation-free rule: __device__ globals)
__device__ __half   g_bufA[(size_t)NMAX * DIM];   // h messages (fp16, unscaled)
__device__ float    g_bufB[(size_t)NMAX * DIM];   // activations (fp32)
__device__ int      g_deg[NMAX];
__device__ float    g_dinv[NMAX];
__device__ int      g_rowptr[NMAX + 1];
__device__ int      g_cursor[NMAX];
__device__ int      g_csrc[EMAX];
__device__ int      g_bsum[512];
__device__ int      g_is64;
__device__ uint32_t g_Wimg[2][8192];              // [layer][swizzled fp16x2 image]

// ======================= helpers =======================
__device__ __forceinline__ uint32_t smem_u32(const void* p) {
    uint32_t a;
    asm("{ .reg .u64 t; cvta.to.shared.u64 t, %1; cvt.u32.u64 %0, t; }" : "=r"(a) : "l"(p));
    return a;
}

// Blocked SW128 atom layout for a [rows=128, K=128] 16-bit tile.
__host__ __device__ __forceinline__ uint32_t blk_off(int row, int col /*elem idx*/) {
    uint32_t off = (uint32_t)((row >> 3) + (col >> 6) * 16) * 1024u
                 + (uint32_t)(row & 7) * 128u + (uint32_t)(col & 63) * 2u;
    return off ^ ((off >> 3) & 0x70u);
}

__device__ __forceinline__ void ldsm4(uint32_t* r, uint32_t addr) {
    asm volatile("ldmatrix.sync.aligned.m8n8.x4.shared.b16 {%0,%1,%2,%3}, [%4];"
                 : "=r"(r[0]), "=r"(r[1]), "=r"(r[2]), "=r"(r[3]) : "r"(addr));
}

__device__ __forceinline__ void mma_f16(float* d, const uint32_t* a,
                                        uint32_t b0, uint32_t b1) {
    asm volatile(
        "mma.sync.aligned.m16n8k16.row.col.f32.f16.f16.f32 "
        "{%0,%1,%2,%3}, {%4,%5,%6,%7}, {%8,%9}, {%0,%1,%2,%3};"
        : "+f"(d[0]), "+f"(d[1]), "+f"(d[2]), "+f"(d[3])
        : "r"(a[0]), "r"(a[1]), "r"(a[2]), "r"(a[3]), "r"(b0), "r"(b1));
}

// ======================= index dtype detection =======================
__global__ void detect_kernel(const unsigned int* __restrict__ p) {
    if (threadIdx.x == 0 && blockIdx.x == 0) {
        int is64 = 1;
        #pragma unroll
        for (int i = 0; i < 64; i++)
            if (p[2 * i + 1] != 0u) is64 = 0;
        g_is64 = is64;
    }
}

__device__ __forceinline__ int ld_idx(const void* p, long long i) {
    if (g_is64) return (int)((const long long*)p)[i];
    return ((const int*)p)[i];
}

// ======================= degree =======================
__global__ void deg_count(const void* __restrict__ ei, long long E) {
    long long i = (long long)blockIdx.x * blockDim.x + threadIdx.x;
    if (i < E) atomicAdd(&g_deg[ld_idx(ei, E + i)], 1);
}

// ======================= prefix scan -> CSR (+ dinv fused) =======================
__global__ void scan_partial(int n) {
    int i = blockIdx.x * 256 + threadIdx.x;
    int v = (i < n) ? g_deg[i] : 0;
    if (i < n) g_dinv[i] = rsqrtf((float)(v + 1));  // fused dinv (+1 self loop)
    int s = v;
    #pragma unroll
    for (int o = 16; o; o >>= 1) s += __shfl_down_sync(0xffffffffu, s, o);
    __shared__ int ws[8];
    if ((threadIdx.x & 31) == 0) ws[threadIdx.x >> 5] = s;
    __syncthreads();
    if (threadIdx.x == 0) {
        int t = 0;
        #pragma unroll
        for (int k = 0; k < 8; k++) t += ws[k];
        g_bsum[blockIdx.x] = t;
    }
}

__global__ void scan_top(int nb) {
    __shared__ int sh[512];
    int t = threadIdx.x;
    int v = (t < nb) ? g_bsum[t] : 0;
    sh[t] = v;
    __syncthreads();
    #pragma unroll
    for (int o = 1; o < 512; o <<= 1) {
        int u = (t >= o) ? sh[t - o] : 0;
        __syncthreads();
        sh[t] += u;
        __syncthreads();
    }
    if (t < nb) g_bsum[t] = sh[t] - v;
}

__global__ void scan_final(int n, long long E) {
    int t = threadIdx.x, lane = t & 31, wid = t >> 5;
    int i = blockIdx.x * 256 + t;
    int v = (i < n) ? g_deg[i] : 0;
    int incl = v;
    #pragma unroll
    for (int o = 1; o < 32; o <<= 1) {
        int u = __shfl_up_sync(0xffffffffu, incl, o);
        if (lane >= o) incl += u;
    }
    __shared__ int ws[8], wso[8];
    if (lane == 31) ws[wid] = incl;
    __syncthreads();
    if (t == 0) {
        int s = 0;
        #pragma unroll
        for (int k = 0; k < 8; k++) { wso[k] = s; s += ws[k]; }
    }
    __syncthreads();
    int excl = incl - v + wso[wid] + g_bsum[blockIdx.x];
    if (i < n) { g_rowptr[i] = excl; g_cursor[i] = excl; }
    if (i == n - 1) g_rowptr[n] = (int)E;
}

__global__ void fill_kernel(const void* __restrict__ ei, long long E) {
    long long i = (long long)blockIdx.x * blockDim.x + threadIdx.x;
    if (i >= E) return;
    int s = ld_idx(ei, i);
    int d = ld_idx(ei, E + i);
    int pos = atomicAdd(&g_cursor[d], 1);
    g_csrc[pos] = s;
}

// ======================= W transpose into swizzled fp16 images =======================
__global__ void wprep(const float* __restrict__ W1, const float* __restrict__ W2,
                      uint32_t* __restrict__ img) {
    int i = blockIdx.x * 256 + threadIdx.x;      // 2 layers * 128 n * 64 k2
    if (i >= 16384) return;
    int l = i >> 13, rem = i & 8191;
    int nrow = rem >> 6, k2 = rem & 63;
    const float* W = l ? W2 : W1;
    float x0 = W[(2 * k2) * 128 + nrow];
    float x1 = W[(2 * k2 + 1) * 128 + nrow];
    __half2 hv = __floats2half2_rn(x0, x1);      // low = even col
    uint32_t widx = blk_off(nrow, 2 * k2) >> 2;
    img[l * 8192 + widx] = *(uint32_t*)&hv;
}

// ======================= HMMA GEMM (single-pass fp16): outA = fp16(X @ W) =======================
#define SM_A 0
#define SM_B 32768
#define GEMM_SMEM 65536

__global__ void __launch_bounds__(256)
gemm_tc(const float* __restrict__ X, const uint32_t* __restrict__ Wimg,
        __half* __restrict__ outA, int n) {
    extern __shared__ char sm[];
    uint32_t smem_base = smem_u32(sm);
    int t = threadIdx.x;
    int w = t >> 5, lane = t & 31;
    int row0 = blockIdx.x * 128;

    // ---- load X tile, convert to fp16, write blocked+swizzled SMEM ----
    {
        int lrow = t >> 1;
        int kh = t & 1;
        int row = row0 + lrow;
        const float4* X4 = (const float4*)X;
        #pragma unroll 4
        for (int i = 0; i < 16; i++) {
            float4 v = (row < n) ? X4[(size_t)row * 32 + kh * 16 + i]
                                 : make_float4(0.f, 0.f, 0.f, 0.f);
            int k = kh * 64 + i * 4;
            __half2 p0 = __floats2half2_rn(v.x, v.y);
            __half2 p1 = __floats2half2_rn(v.z, v.w);
            *(uint32_t*)(sm + SM_A + blk_off(lrow, k))     = *(uint32_t*)&p0;
            *(uint32_t*)(sm + SM_A + blk_off(lrow, k + 2)) = *(uint32_t*)&p1;
        }
    }
    // ---- copy pre-swizzled W image (32KB) ----
    {
        const uint4* s4 = (const uint4*)Wimg;
        uint4* d4 = (uint4*)(sm + SM_B);
        #pragma unroll
        for (int i = 0; i < 8; i++) d4[t + 256 * i] = s4[t + 256 * i];
    }
    __syncthreads();

    int mwarp = (w & 3) * 32;
    int nwarp = (w >> 2) * 64;

    float acc[2][8][4];
    #pragma unroll
    for (int mi = 0; mi < 2; mi++)
        #pragma unroll
        for (int nj = 0; nj < 8; nj++)
            #pragma unroll
            for (int q = 0; q < 4; q++) acc[mi][nj][q] = 0.f;

    int a_row = mwarp + (lane & 15);
    int a_kof = (lane >> 4) << 3;
    int b_row = nwarp + (lane & 7) + ((lane >> 4) << 3);
    int b_kof = (lane & 8);

    uint32_t Abase = smem_base + SM_A;
    uint32_t Bbase = smem_base + SM_B;

    #pragma unroll
    for (int ks = 0; ks < 8; ks++) {
        int k0 = ks * 16;
        uint32_t a[2][4];
        ldsm4(a[0], Abase + blk_off(a_row,      k0 + a_kof));
        ldsm4(a[1], Abase + blk_off(a_row + 16, k0 + a_kof));
        uint32_t b[4][4];
        #pragma unroll
        for (int g = 0; g < 4; g++)
            ldsm4(b[g], Bbase + blk_off(b_row + g * 16, k0 + b_kof));
        #pragma unroll
        for (int mi = 0; mi < 2; mi++)
            #pragma unroll
            for (int g = 0; g < 4; g++) {
                mma_f16(acc[mi][2 * g],     a[mi], b[g][0], b[g][1]);
                mma_f16(acc[mi][2 * g + 1], a[mi], b[g][2], b[g][3]);
            }
    }

    // ---- epilogue: store raw h as fp16 ----
    {
        int g = lane >> 2, i2 = lane & 3;
        #pragma unroll
        for (int mi = 0; mi < 2; mi++) {
            int r0 = row0 + mwarp + mi * 16 + g;
            int r1 = r0 + 8;
            #pragma unroll
            for (int nj = 0; nj < 8; nj++) {
                int c = nwarp + nj * 8 + 2 * i2;
                if (r0 < n)
                    *(__half2*)(outA + (size_t)r0 * 128 + c) =
                        __floats2half2_rn(acc[mi][nj][0], acc[mi][nj][1]);
                if (r1 < n)
                    *(__half2*)(outA + (size_t)r1 * 128 + c) =
                        __floats2half2_rn(acc[mi][nj][2], acc[mi][nj][3]);
            }
        }
    }
}

// ======================= CSR gather (fp16 messages, fp32 accum) =======================
__global__ void gather_kernel(const __half* __restrict__ A, float* __restrict__ B,
                              const float* __restrict__ bias, int n, int relu) {
    int node = blockIdx.x * (blockDim.x >> 5) + (threadIdx.x >> 5);
    int lane = threadIdx.x & 31;
    if (node >= n) return;
    int beg = g_rowptr[node], end = g_rowptr[node + 1];
    const uint2* A2 = (const uint2*)A;   // 32 uint2 per row

    float dself = g_dinv[node];
    float4 acc;
    {
        uint2 u = A2[(size_t)node * 32 + lane];
        float2 p0 = __half22float2(*(const __half2*)&u.x);
        float2 p1 = __half22float2(*(const __half2*)&u.y);
        acc.x = p0.x * dself; acc.y = p0.y * dself;
        acc.z = p1.x * dself; acc.w = p1.y * dself;
    }

    for (int j0 = beg; j0 < end; j0 += 32) {
        int m = min(32, end - j0);
        int idx = 0; float dv = 0.f;
        if (lane < m) {
            idx = g_csrc[j0 + lane];
            dv = g_dinv[idx];
        }
        int k = 0;
        for (; k + 4 <= m; k += 4) {
            int s0 = __shfl_sync(0xffffffffu, idx, k);
            int s1 = __shfl_sync(0xffffffffu, idx, k + 1);
            int s2 = __shfl_sync(0xffffffffu, idx, k + 2);
            int s3 = __shfl_sync(0xffffffffu, idx, k + 3);
            float d0 = __shfl_sync(0xffffffffu, dv, k);
            float d1 = __shfl_sync(0xffffffffu, dv, k + 1);
            float d2 = __shfl_sync(0xffffffffu, dv, k + 2);
            float d3 = __shfl_sync(0xffffffffu, dv, k + 3);
            uint2 u0 = A2[(size_t)s0 * 32 + lane];
            uint2 u1 = A2[(size_t)s1 * 32 + lane];
            uint2 u2 = A2[(size_t)s2 * 32 + lane];
            uint2 u3 = A2[(size_t)s3 * 32 + lane];
            float2 a0 = __half22float2(*(const __half2*)&u0.x);
            float2 b0v = __half22float2(*(const __half2*)&u0.y);
            float2 a1 = __half22float2(*(const __half2*)&u1.x);
            float2 b1v = __half22float2(*(const __half2*)&u1.y);
            float2 a2 = __half22float2(*(const __half2*)&u2.x);
            float2 b2v = __half22float2(*(const __half2*)&u2.y);
            float2 a3 = __half22float2(*(const __half2*)&u3.x);
            float2 b3v = __half22float2(*(const __half2*)&u3.y);
            acc.x = fmaf(a0.x, d0, fmaf(a1.x, d1, fmaf(a2.x, d2, fmaf(a3.x, d3, acc.x))));
            acc.y = fmaf(a0.y, d0, fmaf(a1.y, d1, fmaf(a2.y, d2, fmaf(a3.y, d3, acc.y))));
            acc.z = fmaf(b0v.x, d0, fmaf(b1v.x, d1, fmaf(b2v.x, d2, fmaf(b3v.x, d3, acc.z))));
            acc.w = fmaf(b0v.y, d0, fmaf(b1v.y, d1, fmaf(b2v.y, d2, fmaf(b3v.y, d3, acc.w))));
        }
        for (; k < m; k++) {
            int s = __shfl_sync(0xffffffffu, idx, k);
            float d = __shfl_sync(0xffffffffu, dv, k);
            uint2 u = A2[(size_t)s * 32 + lane];
            float2 p0 = __half22float2(*(const __half2*)&u.x);
            float2 p1 = __half22float2(*(const __half2*)&u.y);
            acc.x = fmaf(p0.x, d, acc.x);
            acc.y = fmaf(p0.y, d, acc.y);
            acc.z = fmaf(p1.x, d, acc.z);
            acc.w = fmaf(p1.y, d, acc.w);
        }
    }

    float4 bb = ((const float4*)bias)[lane];
    float4 o;
    o.x = fmaf(acc.x, dself, bb.x);
    o.y = fmaf(acc.y, dself, bb.y);
    o.z = fmaf(acc.z, dself, bb.z);
    o.w = fmaf(acc.w, dself, bb.w);
    if (relu) {
        o.x = fmaxf(o.x, 0.f); o.y = fmaxf(o.y, 0.f);
        o.z = fmaxf(o.z, 0.f); o.w = fmaxf(o.w, 0.f);
    }
    ((float4*)B)[(size_t)node * 32 + lane] = o;
}

// ======================= decode =======================
__global__ void decode_kernel(const void* __restrict__ eli, long long M,
                              const float* __restrict__ Z, float* __restrict__ out) {
    long long w = (long long)blockIdx.x * (blockDim.x >> 5) + (threadIdx.x >> 5);
    int lane = threadIdx.x & 31;
    if (w >= M) return;
    int s = 0, d = 0;
    if (lane == 0) {
        s = ld_idx(eli, w);
        d = ld_idx(eli, M + w);
    }
    s = __shfl_sync(0xffffffffu, s, 0);
    d = __shfl_sync(0xffffffffu, d, 0);
    float4 a = ((const float4*)Z)[(size_t)s * 32 + lane];
    float4 b = ((const float4*)Z)[(size_t)d * 32 + lane];
    float sum = a.x * b.x + a.y * b.y + a.z * b.z + a.w * b.w;
    #pragma unroll
    for (int o = 16; o; o >>= 1) sum += __shfl_xor_sync(0xffffffffu, sum, o);
    if (lane == 0) out[w] = sum;
}

// ======================= launch =======================
extern "C" void kernel_launch(void* const* d_in, const int* in_sizes, int n_in,
                              void* d_out, int out_size) {
    const float* x   = (const float*)d_in[0];
    const void*  ei  = d_in[1];
    const void*  eli = d_in[2];
    const float* W1  = (const float*)d_in[3];
    const float* b1  = (const float*)d_in[4];
    const float* W2  = (const float*)d_in[5];
    const float* b2  = (const float*)d_in[6];
    float* out = (float*)d_out;

    int n = in_sizes[0] / DIM;
    long long E = in_sizes[1] / 2;
    long long M = in_sizes[2] / 2;

    __half* pA = nullptr;
    float* pB = nullptr;
    uint32_t* pW = nullptr;
    int* pDeg = nullptr;
    cudaGetSymbolAddress((void**)&pA, g_bufA);
    cudaGetSymbolAddress((void**)&pB, g_bufB);
    cudaGetSymbolAddress((void**)&pW, g_Wimg);
    cudaGetSymbolAddress((void**)&pDeg, g_deg);
    cudaFuncSetAttribute(gemm_tc, cudaFuncAttributeMaxDynamicSharedMemorySize, GEMM_SMEM);

    // Optional side-stream: fall back to single-stream if creation fails.
    static cudaStream_t sB = nullptr;
    static cudaEvent_t evFork = nullptr, evJoin = nullptr;
    static int streamTried = 0;
    if (!streamTried) {
        streamTried = 1;
        if (cudaStreamCreateWithFlags(&sB, cudaStreamNonBlocking) != cudaSuccess) sB = nullptr;
        if (sB) {
            if (cudaEventCreateWithFlags(&evFork, cudaEventDisableTiming) != cudaSuccess ||
                cudaEventCreateWithFlags(&evJoin, cudaEventDisableTiming) != cudaSuccess) {
                sB = nullptr;
            }
        }
        cudaGetLastError();  // clear any sticky-free error state
    }
    cudaStream_t sP = sB ? sB : (cudaStream_t)0;  // preproc stream

    int nb256 = (n + 255) / 256;
    int eb    = (int)((E + 255) / 256);
    int mbw   = (int)((M + 7) / 8);
    int gbw   = (n + 7) / 8;
    int gemmb = (n + 127) / 128;

    // ---- fork: preprocessing on sP, GEMM path on default stream ----
    if (sB) {
        cudaEventRecord(evFork, 0);
        cudaStreamWaitEvent(sB, evFork, 0);
    }

    detect_kernel<<<1, 32, 0, sP>>>((const unsigned int*)ei);
    cudaMemsetAsync(pDeg, 0, (size_t)n * sizeof(int), sP);
    deg_count<<<eb, 256, 0, sP>>>(ei, E);
    scan_partial<<<nb256, 256, 0, sP>>>(n);
    scan_top<<<1, 512, 0, sP>>>(nb256);
    scan_final<<<nb256, 256, 0, sP>>>(n, E);
    fill_kernel<<<eb, 256, 0, sP>>>(ei, E);
    if (sB) cudaEventRecord(evJoin, sB);

    // GEMM path (default stream), independent of the graph structure
    wprep<<<64, 256>>>(W1, W2, pW);
    gemm_tc<<<gemmb, 256, GEMM_SMEM>>>(x, pW, pA, n);

    // ---- join ----
    if (sB) cudaStreamWaitEvent(0, evJoin, 0);

    // Layer 1 aggregate
    gather_kernel<<<gbw, 256>>>(pA, pB, b1, n, 1);

    // Layer 2
    gemm_tc<<<gemmb, 256, GEMM_SMEM>>>(pB, pW + 8192, pA, n);
    gather_kernel<<<gbw, 256>>>(pA, pB, b2, n, 0);

    // Decode
    decode_kernel<<<mbw, 256>>>(eli, M, pB, out);
}

// round 9
// speedup vs baseline: 2.6964x; 1.0585x over previous
#include <cuda_runtime.h>
#include <cuda_bf16.h>
#include <cuda_fp16.h>
#include <math.h>
#include <stdint.h>

#define DIM 128
#define NMAX 100000
#define EMAX 2000000

// Scratch (allocation-free rule: __device__ globals)
__device__ __half   g_bufA[(size_t)NMAX * DIM];   // messages = h*dinv[src] (fp16)
__device__ float    g_bufB[(size_t)NMAX * DIM];   // activations (fp32)
__device__ int      g_deg[NMAX];
__device__ float    g_dinv[NMAX];
__device__ int      g_rowptr[NMAX + 1];
__device__ int      g_cursor[NMAX];
__device__ int      g_csrc[EMAX];
__device__ int      g_bsum[512];
__device__ uint32_t g_Wimg[2][8192];              // [layer][swizzled fp16x2 image]

// ======================= helpers =======================
__device__ __forceinline__ uint32_t smem_u32(const void* p) {
    uint32_t a;
    asm("{ .reg .u64 t; cvta.to.shared.u64 t, %1; cvt.u32.u64 %0, t; }" : "=r"(a) : "l"(p));
    return a;
}

// Blocked SW128 atom layout for a [rows=128, K=128] 16-bit tile.
__host__ __device__ __forceinline__ uint32_t blk_off(int row, int col /*elem idx*/) {
    uint32_t off = (uint32_t)((row >> 3) + (col >> 6) * 16) * 1024u
                 + (uint32_t)(row & 7) * 128u + (uint32_t)(col & 63) * 2u;
    return off ^ ((off >> 3) & 0x70u);
}

__device__ __forceinline__ void ldsm4(uint32_t* r, uint32_t addr) {
    asm volatile("ldmatrix.sync.aligned.m8n8.x4.shared.b16 {%0,%1,%2,%3}, [%4];"
                 : "=r"(r[0]), "=r"(r[1]), "=r"(r[2]), "=r"(r[3]) : "r"(addr));
}

__device__ __forceinline__ void mma_f16(float* d, const uint32_t* a,
                                        uint32_t b0, uint32_t b1) {
    asm volatile(
        "mma.sync.aligned.m16n8k16.row.col.f32.f16.f16.f32 "
        "{%0,%1,%2,%3}, {%4,%5,%6,%7}, {%8,%9}, {%0,%1,%2,%3};"
        : "+f"(d[0]), "+f"(d[1]), "+f"(d[2]), "+f"(d[3])
        : "r"(a[0]), "r"(a[1]), "r"(a[2]), "r"(a[3]), "r"(b0), "r"(b1));
}

// Per-block int64/int32 detection (first 64 entries; values < 2^31 so int64 has
// zero odd words with probability 1 for this data).
__device__ __forceinline__ int block_is64(const void* p) {
    __shared__ int s64;
    if (threadIdx.x == 0) {
        const unsigned int* u = (const unsigned int*)p;
        int e = 1;
        #pragma unroll
        for (int i = 0; i < 64; i++)
            if (u[2 * i + 1] != 0u) e = 0;
        s64 = e;
    }
    __syncthreads();
    return s64;
}

__device__ __forceinline__ int ld_idx2(const void* p, long long i, int is64) {
    return is64 ? (int)((const long long*)p)[i] : ((const int*)p)[i];
}

// ======================= degree (detect fused) =======================
__global__ void deg_count(const void* __restrict__ ei, long long E) {
    int is64 = block_is64(ei);
    long long i = (long long)blockIdx.x * blockDim.x + threadIdx.x;
    if (i < E) atomicAdd(&g_deg[ld_idx2(ei, E + i, is64)], 1);
}

// ======================= scan phase 1 (+ dinv fused) =======================
__global__ void scan_partial(int n) {
    int i = blockIdx.x * 256 + threadIdx.x;
    int v = (i < n) ? g_deg[i] : 0;
    if (i < n) g_dinv[i] = rsqrtf((float)(v + 1));  // +1 self loop
    int s = v;
    #pragma unroll
    for (int o = 16; o; o >>= 1) s += __shfl_down_sync(0xffffffffu, s, o);
    __shared__ int ws[8];
    if ((threadIdx.x & 31) == 0) ws[threadIdx.x >> 5] = s;
    __syncthreads();
    if (threadIdx.x == 0) {
        int t = 0;
        #pragma unroll
        for (int k = 0; k < 8; k++) t += ws[k];
        g_bsum[blockIdx.x] = t;
    }
}

// ======================= scan phase 2 (top-scan fused per block) =======================
__global__ void scan_final(int n, long long E) {
    int t = threadIdx.x, lane = t & 31, wid = t >> 5;

    // block offset = sum of g_bsum[0 .. blockIdx.x)
    __shared__ int s_off;
    {
        int part = 0;
        for (int i = t; i < blockIdx.x; i += 256) part += g_bsum[i];
        #pragma unroll
        for (int o = 16; o; o >>= 1) part += __shfl_down_sync(0xffffffffu, part, o);
        __shared__ int wr[8];
        if (lane == 0) wr[wid] = part;
        __syncthreads();
        if (t == 0) {
            int s = 0;
            #pragma unroll
            for (int k = 0; k < 8; k++) s += wr[k];
            s_off = s;
        }
        __syncthreads();
    }

    int i = blockIdx.x * 256 + t;
    int v = (i < n) ? g_deg[i] : 0;
    int incl = v;
    #pragma unroll
    for (int o = 1; o < 32; o <<= 1) {
        int u = __shfl_up_sync(0xffffffffu, incl, o);
        if (lane >= o) incl += u;
    }
    __shared__ int ws[8], wso[8];
    if (lane == 31) ws[wid] = incl;
    __syncthreads();
    if (t == 0) {
        int s = 0;
        #pragma unroll
        for (int k = 0; k < 8; k++) { wso[k] = s; s += ws[k]; }
    }
    __syncthreads();
    int excl = incl - v + wso[wid] + s_off;
    if (i < n) { g_rowptr[i] = excl; g_cursor[i] = excl; }
    if (i == n - 1) g_rowptr[n] = (int)E;
}

__global__ void fill_kernel(const void* __restrict__ ei, long long E) {
    int is64 = block_is64(ei);
    long long i = (long long)blockIdx.x * blockDim.x + threadIdx.x;
    if (i >= E) return;
    int s = ld_idx2(ei, i, is64);
    int d = ld_idx2(ei, E + i, is64);
    int pos = atomicAdd(&g_cursor[d], 1);
    g_csrc[pos] = s;
}

// ======================= W transpose into swizzled fp16 images =======================
__global__ void wprep(const float* __restrict__ W1, const float* __restrict__ W2,
                      uint32_t* __restrict__ img) {
    int i = blockIdx.x * 256 + threadIdx.x;      // 2 layers * 128 n * 64 k2
    if (i >= 16384) return;
    int l = i >> 13, rem = i & 8191;
    int nrow = rem >> 6, k2 = rem & 63;
    const float* W = l ? W2 : W1;
    float x0 = W[(2 * k2) * 128 + nrow];
    float x1 = W[(2 * k2 + 1) * 128 + nrow];
    __half2 hv = __floats2half2_rn(x0, x1);      // low = even col
    uint32_t widx = blk_off(nrow, 2 * k2) >> 2;
    img[l * 8192 + widx] = *(uint32_t*)&hv;
}

// ======================= HMMA GEMM: outA = fp16((X @ W) * dinv[row]) =======================
#define SM_A 0
#define SM_B 32768
#define GEMM_SMEM 65536

__global__ void __launch_bounds__(256)
gemm_tc(const float* __restrict__ X, const uint32_t* __restrict__ Wimg,
        __half* __restrict__ outA, int n) {
    extern __shared__ char sm[];
    uint32_t smem_base = smem_u32(sm);
    int t = threadIdx.x;
    int w = t >> 5, lane = t & 31;
    int row0 = blockIdx.x * 128;

    // ---- load X tile, convert to fp16, write blocked+swizzled SMEM ----
    {
        int lrow = t >> 1;
        int kh = t & 1;
        int row = row0 + lrow;
        const float4* X4 = (const float4*)X;
        #pragma unroll 4
        for (int i = 0; i < 16; i++) {
            float4 v = (row < n) ? X4[(size_t)row * 32 + kh * 16 + i]
                                 : make_float4(0.f, 0.f, 0.f, 0.f);
            int k = kh * 64 + i * 4;
            __half2 p0 = __floats2half2_rn(v.x, v.y);
            __half2 p1 = __floats2half2_rn(v.z, v.w);
            *(uint32_t*)(sm + SM_A + blk_off(lrow, k))     = *(uint32_t*)&p0;
            *(uint32_t*)(sm + SM_A + blk_off(lrow, k + 2)) = *(uint32_t*)&p1;
        }
    }
    // ---- copy pre-swizzled W image (32KB) ----
    {
        const uint4* s4 = (const uint4*)Wimg;
        uint4* d4 = (uint4*)(sm + SM_B);
        #pragma unroll
        for (int i = 0; i < 8; i++) d4[t + 256 * i] = s4[t + 256 * i];
    }
    __syncthreads();

    int mwarp = (w & 3) * 32;
    int nwarp = (w >> 2) * 64;

    float acc[2][8][4];
    #pragma unroll
    for (int mi = 0; mi < 2; mi++)
        #pragma unroll
        for (int nj = 0; nj < 8; nj++)
            #pragma unroll
            for (int q = 0; q < 4; q++) acc[mi][nj][q] = 0.f;

    int a_row = mwarp + (lane & 15);
    int a_kof = (lane >> 4) << 3;
    int b_row = nwarp + (lane & 7) + ((lane >> 4) << 3);
    int b_kof = (lane & 8);

    uint32_t Abase = smem_base + SM_A;
    uint32_t Bbase = smem_base + SM_B;

    #pragma unroll
    for (int ks = 0; ks < 8; ks++) {
        int k0 = ks * 16;
        uint32_t a[2][4];
        ldsm4(a[0], Abase + blk_off(a_row,      k0 + a_kof));
        ldsm4(a[1], Abase + blk_off(a_row + 16, k0 + a_kof));
        uint32_t b[4][4];
        #pragma unroll
        for (int g = 0; g < 4; g++)
            ldsm4(b[g], Bbase + blk_off(b_row + g * 16, k0 + b_kof));
        #pragma unroll
        for (int mi = 0; mi < 2; mi++)
            #pragma unroll
            for (int g = 0; g < 4; g++) {
                mma_f16(acc[mi][2 * g],     a[mi], b[g][0], b[g][1]);
                mma_f16(acc[mi][2 * g + 1], a[mi], b[g][2], b[g][3]);
            }
    }

    // ---- epilogue: store msg = h * dinv[row] as fp16 ----
    {
        int g = lane >> 2, i2 = lane & 3;
        #pragma unroll
        for (int mi = 0; mi < 2; mi++) {
            int r0 = row0 + mwarp + mi * 16 + g;
            int r1 = r0 + 8;
            float s0 = (r0 < n) ? g_dinv[r0] : 0.f;
            float s1 = (r1 < n) ? g_dinv[r1] : 0.f;
            #pragma unroll
            for (int nj = 0; nj < 8; nj++) {
                int c = nwarp + nj * 8 + 2 * i2;
                if (r0 < n)
                    *(__half2*)(outA + (size_t)r0 * 128 + c) =
                        __floats2half2_rn(acc[mi][nj][0] * s0, acc[mi][nj][1] * s0);
                if (r1 < n)
                    *(__half2*)(outA + (size_t)r1 * 128 + c) =
                        __floats2half2_rn(acc[mi][nj][2] * s1, acc[mi][nj][3] * s1);
            }
        }
    }
}

// ======================= CSR gather (pre-scaled fp16 messages, fp32 accum) =======================
__global__ void gather_kernel(const __half* __restrict__ A, float* __restrict__ B,
                              const float* __restrict__ bias, int n, int relu) {
    int node = blockIdx.x * (blockDim.x >> 5) + (threadIdx.x >> 5);
    int lane = threadIdx.x & 31;
    if (node >= n) return;
    int beg = g_rowptr[node], end = g_rowptr[node + 1];
    const uint2* A2 = (const uint2*)A;   // 32 uint2 per row

    float4 acc;
    {
        uint2 u = A2[(size_t)node * 32 + lane];   // self msg (already * dinv)
        float2 p0 = __half22float2(*(const __half2*)&u.x);
        float2 p1 = __half22float2(*(const __half2*)&u.y);
        acc.x = p0.x; acc.y = p0.y; acc.z = p1.x; acc.w = p1.y;
    }

    for (int j0 = beg; j0 < end; j0 += 32) {
        int m = min(32, end - j0);
        int idx = (lane < m) ? g_csrc[j0 + lane] : 0;
        int k = 0;
        for (; k + 8 <= m; k += 8) {
            uint2 v[8];
            #pragma unroll
            for (int q = 0; q < 8; q++) {
                int s = __shfl_sync(0xffffffffu, idx, k + q);
                v[q] = A2[(size_t)s * 32 + lane];
            }
            #pragma unroll
            for (int q = 0; q < 8; q++) {
                float2 p0 = __half22float2(*(const __half2*)&v[q].x);
                float2 p1 = __half22float2(*(const __half2*)&v[q].y);
                acc.x += p0.x; acc.y += p0.y; acc.z += p1.x; acc.w += p1.y;
            }
        }
        for (; k < m; k++) {
            int s = __shfl_sync(0xffffffffu, idx, k);
            uint2 u = A2[(size_t)s * 32 + lane];
            float2 p0 = __half22float2(*(const __half2*)&u.x);
            float2 p1 = __half22float2(*(const __half2*)&u.y);
            acc.x += p0.x; acc.y += p0.y; acc.z += p1.x; acc.w += p1.y;
        }
    }

    float sc = g_dinv[node];
    float4 bb = ((const float4*)bias)[lane];
    float4 o;
    o.x = fmaf(acc.x, sc, bb.x);
    o.y = fmaf(acc.y, sc, bb.y);
    o.z = fmaf(acc.z, sc, bb.z);
    o.w = fmaf(acc.w, sc, bb.w);
    if (relu) {
        o.x = fmaxf(o.x, 0.f); o.y = fmaxf(o.y, 0.f);
        o.z = fmaxf(o.z, 0.f); o.w = fmaxf(o.w, 0.f);
    }
    ((float4*)B)[(size_t)node * 32 + lane] = o;
}

// ======================= decode (detect fused) =======================
__global__ void decode_kernel(const void* __restrict__ eli, long long M,
                              const float* __restrict__ Z, float* __restrict__ out) {
    int is64 = block_is64(eli);
    long long w = (long long)blockIdx.x * (blockDim.x >> 5) + (threadIdx.x >> 5);
    int lane = threadIdx.x & 31;
    if (w >= M) return;
    int s = 0, d = 0;
    if (lane == 0) {
        s = ld_idx2(eli, w, is64);
        d = ld_idx2(eli, M + w, is64);
    }
    s = __shfl_sync(0xffffffffu, s, 0);
    d = __shfl_sync(0xffffffffu, d, 0);
    float4 a = ((const float4*)Z)[(size_t)s * 32 + lane];
    float4 b = ((const float4*)Z)[(size_t)d * 32 + lane];
    float sum = a.x * b.x + a.y * b.y + a.z * b.z + a.w * b.w;
    #pragma unroll
    for (int o = 16; o; o >>= 1) sum += __shfl_xor_sync(0xffffffffu, sum, o);
    if (lane == 0) out[w] = sum;
}

// ======================= launch =======================
extern "C" void kernel_launch(void* const* d_in, const int* in_sizes, int n_in,
                              void* d_out, int out_size) {
    const float* x   = (const float*)d_in[0];
    const void*  ei  = d_in[1];
    const void*  eli = d_in[2];
    const float* W1  = (const float*)d_in[3];
    const float* b1  = (const float*)d_in[4];
    const float* W2  = (const float*)d_in[5];
    const float* b2  = (const float*)d_in[6];
    float* out = (float*)d_out;

    int n = in_sizes[0] / DIM;
    long long E = in_sizes[1] / 2;
    long long M = in_sizes[2] / 2;

    __half* pA = nullptr;
    float* pB = nullptr;
    uint32_t* pW = nullptr;
    int* pDeg = nullptr;
    cudaGetSymbolAddress((void**)&pA, g_bufA);
    cudaGetSymbolAddress((void**)&pB, g_bufB);
    cudaGetSymbolAddress((void**)&pW, g_Wimg);
    cudaGetSymbolAddress((void**)&pDeg, g_deg);
    cudaFuncSetAttribute(gemm_tc, cudaFuncAttributeMaxDynamicSharedMemorySize, GEMM_SMEM);

    // Optional side-stream: fall back to single-stream if creation fails.
    static cudaStream_t sB = nullptr;
    static cudaEvent_t evFork = nullptr, evDinv = nullptr, evJoin = nullptr;
    static int streamTried = 0;
    if (!streamTried) {
        streamTried = 1;
        if (cudaStreamCreateWithFlags(&sB, cudaStreamNonBlocking) != cudaSuccess) sB = nullptr;
        if (sB) {
            if (cudaEventCreateWithFlags(&evFork, cudaEventDisableTiming) != cudaSuccess ||
                cudaEventCreateWithFlags(&evDinv, cudaEventDisableTiming) != cudaSuccess ||
                cudaEventCreateWithFlags(&evJoin, cudaEventDisableTiming) != cudaSuccess) {
                sB = nullptr;
            }
        }
        cudaGetLastError();  // clear any sticky-free error state
    }
    cudaStream_t sP = sB ? sB : (cudaStream_t)0;

    int nb256 = (n + 255) / 256;
    int eb    = (int)((E + 255) / 256);
    int mbw   = (int)((M + 7) / 8);
    int gbw   = (n + 7) / 8;
    int gemmb = (n + 127) / 128;

    // (1) wprep on default stream
    wprep<<<64, 256>>>(W1, W2, pW);

    // fork
    if (sB) {
        cudaEventRecord(evFork, 0);
        cudaStreamWaitEvent(sB, evFork, 0);
    }

    // preproc on sP: (2) deg_count, (3) scan_partial [-> dinv ready]
    cudaMemsetAsync(pDeg, 0, (size_t)n * sizeof(int), sP);
    deg_count<<<eb, 256, 0, sP>>>(ei, E);
    scan_partial<<<nb256, 256, 0, sP>>>(n);
    if (sB) cudaEventRecord(evDinv, sB);

    // (4) gemm1 on default stream (needs dinv for epilogue scaling)
    if (sB) cudaStreamWaitEvent(0, evDinv, 0);
    gemm_tc<<<gemmb, 256, GEMM_SMEM>>>(x, pW, pA, n);

    // (5) scan_final, (6) fill on sP
    scan_final<<<nb256, 256, 0, sP>>>(n, E);
    fill_kernel<<<eb, 256, 0, sP>>>(ei, E);
    if (sB) cudaEventRecord(evJoin, sB);

    // join
    if (sB) cudaStreamWaitEvent(0, evJoin, 0);

    // (7) gather1, (8) gemm2, (9) gather2, (10) decode
    gather_kernel<<<gbw, 256>>>(pA, pB, b1, n, 1);
    gemm_tc<<<gemmb, 256, GEMM_SMEM>>>(pB, pW + 8192, pA, n);
    gather_kernel<<<gbw, 256>>>(pA, pB, b2, n, 0);
    decode_kernel<<<mbw, 256>>>(eli, M, pB, out);
}

// round 10
// speedup vs baseline: 2.9349x; 1.0885x over previous
#include <cuda_runtime.h>
#include <cuda_bf16.h>
#include <cuda_fp16.h>
#include <math.h>
#include <stdint.h>

#define DIM 128
#define NMAX 100000
#define EMAX 2000000

// Scratch (allocation-free rule: __device__ globals)
__device__ __half   g_bufA[(size_t)NMAX * DIM];   // messages = h*dinv[src] (fp16)
__device__ __half   g_bufB[(size_t)NMAX * DIM];   // activations (fp16)
__device__ int      g_deg[NMAX];
__device__ float    g_dinv[NMAX];
__device__ int      g_rowptr[NMAX + 1];
__device__ int      g_cursor[NMAX];
__device__ int      g_csrc[EMAX];
__device__ int      g_bsum[512];
__device__ uint32_t g_Wimg[2][8192];              // [layer][swizzled fp16x2 image]

// ======================= helpers =======================
__device__ __forceinline__ uint32_t smem_u32(const void* p) {
    uint32_t a;
    asm("{ .reg .u64 t; cvta.to.shared.u64 t, %1; cvt.u32.u64 %0, t; }" : "=r"(a) : "l"(p));
    return a;
}

// Blocked SW128 atom layout for a [rows=128, K=128] 16-bit tile.
__host__ __device__ __forceinline__ uint32_t blk_off(int row, int col /*elem idx*/) {
    uint32_t off = (uint32_t)((row >> 3) + (col >> 6) * 16) * 1024u
                 + (uint32_t)(row & 7) * 128u + (uint32_t)(col & 63) * 2u;
    return off ^ ((off >> 3) & 0x70u);
}

__device__ __forceinline__ void ldsm4(uint32_t* r, uint32_t addr) {
    asm volatile("ldmatrix.sync.aligned.m8n8.x4.shared.b16 {%0,%1,%2,%3}, [%4];"
                 : "=r"(r[0]), "=r"(r[1]), "=r"(r[2]), "=r"(r[3]) : "r"(addr));
}

__device__ __forceinline__ void mma_f16(float* d, const uint32_t* a,
                                        uint32_t b0, uint32_t b1) {
    asm volatile(
        "mma.sync.aligned.m16n8k16.row.col.f32.f16.f16.f32 "
        "{%0,%1,%2,%3}, {%4,%5,%6,%7}, {%8,%9}, {%0,%1,%2,%3};"
        : "+f"(d[0]), "+f"(d[1]), "+f"(d[2]), "+f"(d[3])
        : "r"(a[0]), "r"(a[1]), "r"(a[2]), "r"(a[3]), "r"(b0), "r"(b1));
}

// Per-block int64/int32 detection (first 64 entries).
__device__ __forceinline__ int block_is64(const void* p) {
    __shared__ int s64;
    if (threadIdx.x == 0) {
        const unsigned int* u = (const unsigned int*)p;
        int e = 1;
        #pragma unroll
        for (int i = 0; i < 64; i++)
            if (u[2 * i + 1] != 0u) e = 0;
        s64 = e;
    }
    __syncthreads();
    return s64;
}

__device__ __forceinline__ int ld_idx2(const void* p, long long i, int is64) {
    return is64 ? (int)((const long long*)p)[i] : ((const int*)p)[i];
}

// ======================= degree (detect fused) =======================
__global__ void deg_count(const void* __restrict__ ei, long long E) {
    int is64 = block_is64(ei);
    long long i = (long long)blockIdx.x * blockDim.x + threadIdx.x;
    if (i < E) atomicAdd(&g_deg[ld_idx2(ei, E + i, is64)], 1);
}

// ======================= scan phase 1 (+ dinv fused) =======================
__global__ void scan_partial(int n) {
    int i = blockIdx.x * 256 + threadIdx.x;
    int v = (i < n) ? g_deg[i] : 0;
    if (i < n) g_dinv[i] = rsqrtf((float)(v + 1));  // +1 self loop
    int s = v;
    #pragma unroll
    for (int o = 16; o; o >>= 1) s += __shfl_down_sync(0xffffffffu, s, o);
    __shared__ int ws[8];
    if ((threadIdx.x & 31) == 0) ws[threadIdx.x >> 5] = s;
    __syncthreads();
    if (threadIdx.x == 0) {
        int t = 0;
        #pragma unroll
        for (int k = 0; k < 8; k++) t += ws[k];
        g_bsum[blockIdx.x] = t;
    }
}

// ======================= scan phase 2 (top-scan fused per block) =======================
__global__ void scan_final(int n, long long E) {
    int t = threadIdx.x, lane = t & 31, wid = t >> 5;

    __shared__ int s_off;
    {
        int part = 0;
        for (int i = t; i < blockIdx.x; i += 256) part += g_bsum[i];
        #pragma unroll
        for (int o = 16; o; o >>= 1) part += __shfl_down_sync(0xffffffffu, part, o);
        __shared__ int wr[8];
        if (lane == 0) wr[wid] = part;
        __syncthreads();
        if (t == 0) {
            int s = 0;
            #pragma unroll
            for (int k = 0; k < 8; k++) s += wr[k];
            s_off = s;
        }
        __syncthreads();
    }

    int i = blockIdx.x * 256 + t;
    int v = (i < n) ? g_deg[i] : 0;
    int incl = v;
    #pragma unroll
    for (int o = 1; o < 32; o <<= 1) {
        int u = __shfl_up_sync(0xffffffffu, incl, o);
        if (lane >= o) incl += u;
    }
    __shared__ int ws[8], wso[8];
    if (lane == 31) ws[wid] = incl;
    __syncthreads();
    if (t == 0) {
        int s = 0;
        #pragma unroll
        for (int k = 0; k < 8; k++) { wso[k] = s; s += ws[k]; }
    }
    __syncthreads();
    int excl = incl - v + wso[wid] + s_off;
    if (i < n) { g_rowptr[i] = excl; g_cursor[i] = excl; }
    if (i == n - 1) g_rowptr[n] = (int)E;
}

__global__ void fill_kernel(const void* __restrict__ ei, long long E) {
    int is64 = block_is64(ei);
    long long i = (long long)blockIdx.x * blockDim.x + threadIdx.x;
    if (i >= E) return;
    int s = ld_idx2(ei, i, is64);
    int d = ld_idx2(ei, E + i, is64);
    int pos = atomicAdd(&g_cursor[d], 1);
    g_csrc[pos] = s;
}

// ======================= W transpose into swizzled fp16 images =======================
__global__ void wprep(const float* __restrict__ W1, const float* __restrict__ W2,
                      uint32_t* __restrict__ img) {
    int i = blockIdx.x * 256 + threadIdx.x;      // 2 layers * 128 n * 64 k2
    if (i >= 16384) return;
    int l = i >> 13, rem = i & 8191;
    int nrow = rem >> 6, k2 = rem & 63;
    const float* W = l ? W2 : W1;
    float x0 = W[(2 * k2) * 128 + nrow];
    float x1 = W[(2 * k2 + 1) * 128 + nrow];
    __half2 hv = __floats2half2_rn(x0, x1);      // low = even col
    uint32_t widx = blk_off(nrow, 2 * k2) >> 2;
    img[l * 8192 + widx] = *(uint32_t*)&hv;
}

// ======================= HMMA GEMM: outA = fp16((X @ W) * dinv[row]) =======================
// FP16IN=false: X is fp32 [n,128]; FP16IN=true: X is fp16 [n,128].
#define SM_A 0
#define SM_B 32768
#define GEMM_SMEM 65536

template<bool FP16IN>
__global__ void __launch_bounds__(256, 2)
gemm_tc(const void* __restrict__ Xv, const uint32_t* __restrict__ Wimg,
        __half* __restrict__ outA, int n) {
    extern __shared__ char sm[];
    uint32_t smem_base = smem_u32(sm);
    int t = threadIdx.x;
    int w = t >> 5, lane = t & 31;
    int row0 = blockIdx.x * 128;

    // ---- load X tile into blocked+swizzled SMEM (fp16) ----
    {
        int lrow = t >> 1;
        int kh = t & 1;
        int row = row0 + lrow;
        #pragma unroll 4
        for (int i = 0; i < 16; i++) {
            int k = kh * 64 + i * 4;
            uint32_t u0, u1;
            if (FP16IN) {
                uint2 v = (row < n) ? ((const uint2*)Xv)[(size_t)row * 32 + kh * 16 + i]
                                    : make_uint2(0u, 0u);
                u0 = v.x; u1 = v.y;
            } else {
                float4 v = (row < n) ? ((const float4*)Xv)[(size_t)row * 32 + kh * 16 + i]
                                     : make_float4(0.f, 0.f, 0.f, 0.f);
                __half2 p0 = __floats2half2_rn(v.x, v.y);
                __half2 p1 = __floats2half2_rn(v.z, v.w);
                u0 = *(uint32_t*)&p0; u1 = *(uint32_t*)&p1;
            }
            *(uint32_t*)(sm + SM_A + blk_off(lrow, k))     = u0;
            *(uint32_t*)(sm + SM_A + blk_off(lrow, k + 2)) = u1;
        }
    }
    // ---- copy pre-swizzled W image (32KB) ----
    {
        const uint4* s4 = (const uint4*)Wimg;
        uint4* d4 = (uint4*)(sm + SM_B);
        #pragma unroll
        for (int i = 0; i < 8; i++) d4[t + 256 * i] = s4[t + 256 * i];
    }
    __syncthreads();

    int mwarp = (w & 3) * 32;
    int nwarp = (w >> 2) * 64;

    float acc[2][8][4];
    #pragma unroll
    for (int mi = 0; mi < 2; mi++)
        #pragma unroll
        for (int nj = 0; nj < 8; nj++)
            #pragma unroll
            for (int q = 0; q < 4; q++) acc[mi][nj][q] = 0.f;

    int a_row = mwarp + (lane & 15);
    int a_kof = (lane >> 4) << 3;
    int b_row = nwarp + (lane & 7) + ((lane >> 4) << 3);
    int b_kof = (lane & 8);

    uint32_t Abase = smem_base + SM_A;
    uint32_t Bbase = smem_base + SM_B;

    #pragma unroll
    for (int ks = 0; ks < 8; ks++) {
        int k0 = ks * 16;
        uint32_t a[2][4];
        ldsm4(a[0], Abase + blk_off(a_row,      k0 + a_kof));
        ldsm4(a[1], Abase + blk_off(a_row + 16, k0 + a_kof));
        uint32_t b[4][4];
        #pragma unroll
        for (int g = 0; g < 4; g++)
            ldsm4(b[g], Bbase + blk_off(b_row + g * 16, k0 + b_kof));
        #pragma unroll
        for (int mi = 0; mi < 2; mi++)
            #pragma unroll
            for (int g = 0; g < 4; g++) {
                mma_f16(acc[mi][2 * g],     a[mi], b[g][0], b[g][1]);
                mma_f16(acc[mi][2 * g + 1], a[mi], b[g][2], b[g][3]);
            }
    }

    // ---- epilogue: store msg = h * dinv[row] as fp16 ----
    {
        int g = lane >> 2, i2 = lane & 3;
        #pragma unroll
        for (int mi = 0; mi < 2; mi++) {
            int r0 = row0 + mwarp + mi * 16 + g;
            int r1 = r0 + 8;
            float s0 = (r0 < n) ? g_dinv[r0] : 0.f;
            float s1 = (r1 < n) ? g_dinv[r1] : 0.f;
            #pragma unroll
            for (int nj = 0; nj < 8; nj++) {
                int c = nwarp + nj * 8 + 2 * i2;
                if (r0 < n)
                    *(__half2*)(outA + (size_t)r0 * 128 + c) =
                        __floats2half2_rn(acc[mi][nj][0] * s0, acc[mi][nj][1] * s0);
                if (r1 < n)
                    *(__half2*)(outA + (size_t)r1 * 128 + c) =
                        __floats2half2_rn(acc[mi][nj][2] * s1, acc[mi][nj][3] * s1);
            }
        }
    }
}

// ======================= CSR gather (fp16 msgs -> fp16 activations) =======================
__global__ void gather_kernel(const __half* __restrict__ A, __half* __restrict__ B,
                              const float* __restrict__ bias, int n, int relu) {
    int node = blockIdx.x * (blockDim.x >> 5) + (threadIdx.x >> 5);
    int lane = threadIdx.x & 31;
    if (node >= n) return;
    int beg = g_rowptr[node], end = g_rowptr[node + 1];
    const uint2* A2 = (const uint2*)A;   // 32 uint2 per row

    float4 acc;
    {
        uint2 u = A2[(size_t)node * 32 + lane];   // self msg (already * dinv)
        float2 p0 = __half22float2(*(const __half2*)&u.x);
        float2 p1 = __half22float2(*(const __half2*)&u.y);
        acc.x = p0.x; acc.y = p0.y; acc.z = p1.x; acc.w = p1.y;
    }

    for (int j0 = beg; j0 < end; j0 += 32) {
        int m = min(32, end - j0);
        int idx = (lane < m) ? g_csrc[j0 + lane] : 0;
        int k = 0;
        for (; k + 8 <= m; k += 8) {
            uint2 v[8];
            #pragma unroll
            for (int q = 0; q < 8; q++) {
                int s = __shfl_sync(0xffffffffu, idx, k + q);
                v[q] = A2[(size_t)s * 32 + lane];
            }
            #pragma unroll
            for (int q = 0; q < 8; q++) {
                float2 p0 = __half22float2(*(const __half2*)&v[q].x);
                float2 p1 = __half22float2(*(const __half2*)&v[q].y);
                acc.x += p0.x; acc.y += p0.y; acc.z += p1.x; acc.w += p1.y;
            }
        }
        for (; k < m; k++) {
            int s = __shfl_sync(0xffffffffu, idx, k);
            uint2 u = A2[(size_t)s * 32 + lane];
            float2 p0 = __half22float2(*(const __half2*)&u.x);
            float2 p1 = __half22float2(*(const __half2*)&u.y);
            acc.x += p0.x; acc.y += p0.y; acc.z += p1.x; acc.w += p1.y;
        }
    }

    float sc = g_dinv[node];
    float4 bb = ((const float4*)bias)[lane];
    float4 o;
    o.x = fmaf(acc.x, sc, bb.x);
    o.y = fmaf(acc.y, sc, bb.y);
    o.z = fmaf(acc.z, sc, bb.z);
    o.w = fmaf(acc.w, sc, bb.w);
    if (relu) {
        o.x = fmaxf(o.x, 0.f); o.y = fmaxf(o.y, 0.f);
        o.z = fmaxf(o.z, 0.f); o.w = fmaxf(o.w, 0.f);
    }
    __half2 h0 = __floats2half2_rn(o.x, o.y);
    __half2 h1 = __floats2half2_rn(o.z, o.w);
    uint2 ov = make_uint2(*(uint32_t*)&h0, *(uint32_t*)&h1);
    ((uint2*)B)[(size_t)node * 32 + lane] = ov;
}

// ======================= decode (fp16 z, detect fused) =======================
__global__ void decode_kernel(const void* __restrict__ eli, long long M,
                              const __half* __restrict__ Z, float* __restrict__ out) {
    int is64 = block_is64(eli);
    long long w = (long long)blockIdx.x * (blockDim.x >> 5) + (threadIdx.x >> 5);
    int lane = threadIdx.x & 31;
    if (w >= M) return;
    int s = 0, d = 0;
    if (lane == 0) {
        s = ld_idx2(eli, w, is64);
        d = ld_idx2(eli, M + w, is64);
    }
    s = __shfl_sync(0xffffffffu, s, 0);
    d = __shfl_sync(0xffffffffu, d, 0);
    const uint2* Z2 = (const uint2*)Z;
    uint2 ua = Z2[(size_t)s * 32 + lane];
    uint2 ub = Z2[(size_t)d * 32 + lane];
    float2 a0 = __half22float2(*(const __half2*)&ua.x);
    float2 a1 = __half22float2(*(const __half2*)&ua.y);
    float2 b0 = __half22float2(*(const __half2*)&ub.x);
    float2 b1 = __half22float2(*(const __half2*)&ub.y);
    float sum = a0.x * b0.x + a0.y * b0.y + a1.x * b1.x + a1.y * b1.y;
    #pragma unroll
    for (int o = 16; o; o >>= 1) sum += __shfl_xor_sync(0xffffffffu, sum, o);
    if (lane == 0) out[w] = sum;
}

// ======================= launch =======================
extern "C" void kernel_launch(void* const* d_in, const int* in_sizes, int n_in,
                              void* d_out, int out_size) {
    const float* x   = (const float*)d_in[0];
    const void*  ei  = d_in[1];
    const void*  eli = d_in[2];
    const float* W1  = (const float*)d_in[3];
    const float* b1  = (const float*)d_in[4];
    const float* W2  = (const float*)d_in[5];
    const float* b2  = (const float*)d_in[6];
    float* out = (float*)d_out;

    int n = in_sizes[0] / DIM;
    long long E = in_sizes[1] / 2;
    long long M = in_sizes[2] / 2;

    __half *pA = nullptr, *pB = nullptr;
    uint32_t* pW = nullptr;
    int* pDeg = nullptr;
    cudaGetSymbolAddress((void**)&pA, g_bufA);
    cudaGetSymbolAddress((void**)&pB, g_bufB);
    cudaGetSymbolAddress((void**)&pW, g_Wimg);
    cudaGetSymbolAddress((void**)&pDeg, g_deg);
    cudaFuncSetAttribute(gemm_tc<false>, cudaFuncAttributeMaxDynamicSharedMemorySize, GEMM_SMEM);
    cudaFuncSetAttribute(gemm_tc<true>,  cudaFuncAttributeMaxDynamicSharedMemorySize, GEMM_SMEM);

    // Optional side-stream: fall back to single-stream if creation fails.
    static cudaStream_t sB = nullptr;
    static cudaEvent_t evFork = nullptr, evDinv = nullptr, evJoin = nullptr;
    static int streamTried = 0;
    if (!streamTried) {
        streamTried = 1;
        if (cudaStreamCreateWithFlags(&sB, cudaStreamNonBlocking) != cudaSuccess) sB = nullptr;
        if (sB) {
            if (cudaEventCreateWithFlags(&evFork, cudaEventDisableTiming) != cudaSuccess ||
                cudaEventCreateWithFlags(&evDinv, cudaEventDisableTiming) != cudaSuccess ||
                cudaEventCreateWithFlags(&evJoin, cudaEventDisableTiming) != cudaSuccess) {
                sB = nullptr;
            }
        }
        cudaGetLastError();
    }
    cudaStream_t sP = sB ? sB : (cudaStream_t)0;

    int nb256 = (n + 255) / 256;
    int eb    = (int)((E + 255) / 256);
    int mbw   = (int)((M + 7) / 8);
    int gbw   = (n + 7) / 8;
    int gemmb = (n + 127) / 128;

    // (1) wprep on default stream
    wprep<<<64, 256>>>(W1, W2, pW);

    // fork
    if (sB) {
        cudaEventRecord(evFork, 0);
        cudaStreamWaitEvent(sB, evFork, 0);
    }

    // preproc on sP
    cudaMemsetAsync(pDeg, 0, (size_t)n * sizeof(int), sP);
    deg_count<<<eb, 256, 0, sP>>>(ei, E);
    scan_partial<<<nb256, 256, 0, sP>>>(n);
    if (sB) cudaEventRecord(evDinv, sB);

    // gemm1 on default stream (needs dinv in epilogue)
    if (sB) cudaStreamWaitEvent(0, evDinv, 0);
    gemm_tc<false><<<gemmb, 256, GEMM_SMEM>>>(x, pW, pA, n);

    // scan_final + fill on sP
    scan_final<<<nb256, 256, 0, sP>>>(n, E);
    fill_kernel<<<eb, 256, 0, sP>>>(ei, E);
    if (sB) cudaEventRecord(evJoin, sB);

    // join
    if (sB) cudaStreamWaitEvent(0, evJoin, 0);

    // gather1, gemm2, gather2, decode
    gather_kernel<<<gbw, 256>>>(pA, pB, b1, n, 1);
    gemm_tc<true><<<gemmb, 256, GEMM_SMEM>>>(pB, pW + 8192, pA, n);
    gather_kernel<<<gbw, 256>>>(pA, pB, b2, n, 0);
    decode_kernel<<<mbw, 256>>>(eli, M, pB, out);
}